// round 12
// baseline (speedup 1.0000x reference)
#include <cuda_runtime.h>
#include <cuda_bf16.h>
#include <cstdint>

#define N_ITEMS 30000
#define N_USERS 20000
#define NNODES  50000
#define NEDGES  512000
#define D0 768
#define D1 128
#define D2 64
#define OUTW 960   // 768 + 128 + 64
#define SCANB ((NNODES + 1023) / 1024)   // 49

// ---------------- device scratch (static, no runtime alloc) ----------------
__device__ float g_side0[(size_t)NNODES * D0];   // 153.6 MB
__device__ float g_ego1 [(size_t)NNODES * D1];   // 25.6 MB
__device__ float g_side1[(size_t)NNODES * D1];   // 25.6 MB
__device__ int   g_hist[NNODES];
__device__ int   g_rowptr[NNODES + 1];
__device__ int   g_cursor[NNODES];
__device__ int   g_col_sorted[NEDGES];
__device__ float g_val_sorted[NEDGES];
__device__ int   g_bsum[64];
__device__ int   g_boff[64];
// split + transposed weights for tensor-core gemm0: [N=128][K=768] bf16
__device__ __nv_bfloat16 g_w1hiT[D1 * D0];
__device__ __nv_bfloat16 g_w1loT[D1 * D0];
__device__ __nv_bfloat16 g_w2hiT[D1 * D0];
__device__ __nv_bfloat16 g_w2loT[D1 * D0];

__device__ __forceinline__ float leaky(float v) { return v > 0.f ? v : 0.01f * v; }

__device__ __forceinline__ uint32_t smem_u32(const void* p) {
    uint32_t a;
    asm("{ .reg .u64 t; cvta.to.shared.u64 t, %1; cvt.u32.u64 %0, t; }"
        : "=r"(a) : "l"(p));
    return a;
}
__device__ __forceinline__ void ldsm_x4(uint32_t* r, uint32_t addr) {
    asm volatile("ldmatrix.sync.aligned.m8n8.x4.shared.b16 {%0,%1,%2,%3}, [%4];"
                 : "=r"(r[0]), "=r"(r[1]), "=r"(r[2]), "=r"(r[3]) : "r"(addr));
}
__device__ __forceinline__ void ldsm_x2(uint32_t* r, uint32_t addr) {
    asm volatile("ldmatrix.sync.aligned.m8n8.x2.shared.b16 {%0,%1}, [%2];"
                 : "=r"(r[0]), "=r"(r[1]) : "r"(addr));
}
__device__ __forceinline__ void mma_bf16(float* d, const uint32_t* a, const uint32_t* b) {
    asm volatile(
        "mma.sync.aligned.m16n8k16.row.col.f32.bf16.bf16.f32 "
        "{%0,%1,%2,%3}, {%4,%5,%6,%7}, {%8,%9}, {%0,%1,%2,%3};"
        : "+f"(d[0]), "+f"(d[1]), "+f"(d[2]), "+f"(d[3])
        : "r"(a[0]), "r"(a[1]), "r"(a[2]), "r"(a[3]), "r"(b[0]), "r"(b[1]));
}
__device__ __forceinline__ uint32_t pack_bf16(__nv_bfloat16 a, __nv_bfloat16 b) {
    return ((uint32_t)__bfloat16_as_ushort(b) << 16) | (uint32_t)__bfloat16_as_ushort(a);
}
__device__ __forceinline__ void split_bf16(float x, __nv_bfloat16& hi, __nv_bfloat16& lo) {
    hi = __float2bfloat16(x);
    lo = __float2bfloat16(x - __bfloat162float(hi));
}

// ---------------- CSR build ----------------
__global__ void init_hist_kernel() {
    for (int i = blockIdx.x * blockDim.x + threadIdx.x; i < NNODES;
         i += gridDim.x * blockDim.x)
        g_hist[i] = 0;
}

__global__ void hist_kernel(const int* __restrict__ rows) {
    int e = blockIdx.x * blockDim.x + threadIdx.x;
    if (e < NEDGES) atomicAdd(&g_hist[rows[e]], 1);
}

__global__ void scan_local_kernel() {
    __shared__ int wsum[32];
    int tid = threadIdx.x, lane = tid & 31, wid = tid >> 5;
    int i = blockIdx.x * 1024 + tid;
    int v = (i < NNODES) ? g_hist[i] : 0;
    int x = v;
    #pragma unroll
    for (int off = 1; off < 32; off <<= 1) {
        int t = __shfl_up_sync(0xffffffffu, x, off);
        if (lane >= off) x += t;
    }
    if (lane == 31) wsum[wid] = x;
    __syncthreads();
    if (wid == 0) {
        int w = wsum[lane];
        #pragma unroll
        for (int off = 1; off < 32; off <<= 1) {
            int t = __shfl_up_sync(0xffffffffu, w, off);
            if (lane >= off) w += t;
        }
        wsum[lane] = w;
    }
    __syncthreads();
    int warp_off = (wid == 0) ? 0 : wsum[wid - 1];
    int incl = x + warp_off;
    if (i < NNODES) g_rowptr[i] = incl - v;
    if (tid == 1023) g_bsum[blockIdx.x] = incl;
}

__global__ void scan_bsum_kernel() {   // 1 block, 64 threads
    __shared__ int s[64];
    int tid = threadIdx.x;
    int v = (tid < SCANB) ? g_bsum[tid] : 0;
    s[tid] = v;
    __syncthreads();
    #pragma unroll
    for (int off = 1; off < 64; off <<= 1) {
        int t = (tid >= off) ? s[tid - off] : 0;
        __syncthreads();
        s[tid] += t;
        __syncthreads();
    }
    g_boff[tid] = s[tid] - v;
    if (tid == SCANB - 1) g_rowptr[NNODES] = s[tid];
}

__global__ void scan_add_kernel() {
    int i = blockIdx.x * 1024 + threadIdx.x;
    if (i < NNODES) {
        int val = g_rowptr[i] + g_boff[blockIdx.x];
        g_rowptr[i] = val;
        g_cursor[i] = val;
    }
}

__global__ void scatter_kernel(const int* __restrict__ rows,
                               const int* __restrict__ cols,
                               const float* __restrict__ vals) {
    int e = blockIdx.x * blockDim.x + threadIdx.x;
    if (e < NEDGES) {
        int r = rows[e];
        int p = atomicAdd(&g_cursor[r], 1);
        g_col_sorted[p] = cols[e];
        g_val_sorted[p] = vals[e];
    }
}

// ---------------- W split+transpose prep ----------------
__global__ void wsplit_kernel(const float* __restrict__ W1,
                              const float* __restrict__ W2) {
    int idx = blockIdx.x * blockDim.x + threadIdx.x;
    if (idx >= D1 * D0) return;
    int n = idx / D0, k = idx - n * D0;
    float w1 = W1[(size_t)k * D1 + n];
    float w2 = W2[(size_t)k * D1 + n];
    __nv_bfloat16 hi, lo;
    split_bf16(w1, hi, lo);
    g_w1hiT[idx] = hi; g_w1loT[idx] = lo;
    split_bf16(w2, hi, lo);
    g_w2hiT[idx] = hi; g_w2loT[idx] = lo;
}

// ---------------- SpMM layer0 (128-wide chunks, unroll 8) ----------------
__global__ __launch_bounds__(256) void spmm0_chunk_kernel(
    const float* __restrict__ item, const float* __restrict__ user) {
    const int w = threadIdx.x >> 5;      // warp -> row
    const int lane = threadIdx.x & 31;   // lane -> 4 cols
    const int r = blockIdx.x * 8 + w;
    const int off = blockIdx.y * 128 + lane * 4;
    if (r >= NNODES) return;
    const int e0 = g_rowptr[r], e1 = g_rowptr[r + 1];
    float4 acc = make_float4(0.f, 0.f, 0.f, 0.f);
    int e = e0;
    const int n8 = e0 + ((e1 - e0) & ~7);
    for (; e < n8; e += 8) {
        const float* p[8];
        float v[8];
        #pragma unroll
        for (int q = 0; q < 8; ++q) {
            int c = g_col_sorted[e + q];
            v[q] = g_val_sorted[e + q];
            p[q] = ((c < N_ITEMS) ? item + (size_t)c * D0
                                  : user + (size_t)(c - N_ITEMS) * D0) + off;
        }
        float4 x[8];
        #pragma unroll
        for (int q = 0; q < 8; ++q) x[q] = __ldg((const float4*)p[q]);
        #pragma unroll
        for (int q = 0; q < 8; ++q) {
            acc.x += v[q] * x[q].x;
            acc.y += v[q] * x[q].y;
            acc.z += v[q] * x[q].z;
            acc.w += v[q] * x[q].w;
        }
    }
    for (; e < e1; ++e) {
        int   c = g_col_sorted[e];
        float v = g_val_sorted[e];
        const float* p = ((c < N_ITEMS) ? item + (size_t)c * D0
                                        : user + (size_t)(c - N_ITEMS) * D0) + off;
        float4 x = __ldg((const float4*)p);
        acc.x += v * x.x; acc.y += v * x.y; acc.z += v * x.z; acc.w += v * x.w;
    }
    *(float4*)(g_side0 + (size_t)r * D0 + off) = acc;
}

// ---------------- fused GEMM layer0 (mma.sync bf16, 3-term split) ----------------
// BM=128, BN=128, BK=16, 256 threads (8 warps 4x2, warp tile 32x64)
// Streams ego0 -> out[:, 0:768]; fuses row-normalize -> out[:, 768:896].
#define APAD 24   // row stride in bf16 (48 B, conflict-free ldmatrix)

// dynamic smem layout (bytes); all offsets 16-aligned
#define G0_AHI  0
#define G0_ALO  (G0_AHI + 128 * APAD * 2)   // 6144 each
#define G0_HHI  (G0_ALO + 128 * APAD * 2)
#define G0_HLO  (G0_HHI + 128 * APAD * 2)
#define G0_W1H  (G0_HLO + 128 * APAD * 2)
#define G0_W1L  (G0_W1H + 128 * APAD * 2)
#define G0_W2H  (G0_W1L + 128 * APAD * 2)
#define G0_W2L  (G0_W2H + 128 * APAD * 2)
#define G0_BS   (G0_W2L + 128 * APAD * 2)   // 128 floats
#define G0_RS   (G0_BS + 512)               // 128 floats
#define GEMM0_SMEM (G0_RS + 512)            // 50176 bytes

__global__ __launch_bounds__(256) void gemm0_mma_kernel(
    const float* __restrict__ item, const float* __restrict__ user,
    const float* __restrict__ b1, const float* __restrict__ b2,
    float* __restrict__ out) {
    extern __shared__ __align__(16) char dsm[];
    __nv_bfloat16* sAhi = (__nv_bfloat16*)(dsm + G0_AHI);
    __nv_bfloat16* sAlo = (__nv_bfloat16*)(dsm + G0_ALO);
    __nv_bfloat16* sHhi = (__nv_bfloat16*)(dsm + G0_HHI);
    __nv_bfloat16* sHlo = (__nv_bfloat16*)(dsm + G0_HLO);
    __nv_bfloat16* sW1h = (__nv_bfloat16*)(dsm + G0_W1H);
    __nv_bfloat16* sW1l = (__nv_bfloat16*)(dsm + G0_W1L);
    __nv_bfloat16* sW2h = (__nv_bfloat16*)(dsm + G0_W2H);
    __nv_bfloat16* sW2l = (__nv_bfloat16*)(dsm + G0_W2L);
    float* bsum  = (float*)(dsm + G0_BS);
    float* rowss = (float*)(dsm + G0_RS);

    const int t    = threadIdx.x;
    const int lane = t & 31;
    const int wid  = t >> 5;
    const int wm   = wid >> 1;           // 0..3 -> M offset wm*32
    const int wn   = wid & 1;            // 0..1 -> N offset wn*64
    const int rm   = blockIdx.x * 128;

    if (t < D1) { bsum[t] = b1[t] + b2[t]; rowss[t] = 0.f; }

    // staging coords: one 8-elem slot per thread covers 128 rows x 16 k
    const int arow = t >> 1;             // 0..127
    const int akq  = (t & 1) * 8;        // 0 or 8
    const int gm   = rm + arow;
    const bool mOk = gm < NNODES;
    const float* sideRow = g_side0 + (size_t)gm * D0 + akq;
    const float* egoRow  = ((gm < N_ITEMS) ? item + (size_t)gm * D0
                                           : user + (size_t)(gm - N_ITEMS) * D0) + akq;
    float* outRow = out + (size_t)gm * OUTW + akq;

    // W staging: one slot per thread covers 16 k x 128 n per plane
    const int wn_row = t >> 1;           // n 0..127
    const int wkq    = (t & 1) * 8;      // k 0 or 8

    // ldmatrix addresses
    const uint32_t aOff = (uint32_t)(((wm * 32 + (lane & 15)) * APAD + (lane >> 4) * 8) * 2);
    const uint32_t addrAhi = smem_u32(sAhi) + aOff;
    const uint32_t addrAlo = smem_u32(sAlo) + aOff;
    const uint32_t addrHhi = smem_u32(sHhi) + aOff;
    const uint32_t addrHlo = smem_u32(sHlo) + aOff;
    const uint32_t bOff = (uint32_t)(((wn * 64 + (lane & 7)) * APAD + ((lane >> 3) & 1) * 8) * 2);
    const uint32_t addrW1h = smem_u32(sW1h) + bOff;
    const uint32_t addrW1l = smem_u32(sW1l) + bOff;
    const uint32_t addrW2h = smem_u32(sW2h) + bOff;
    const uint32_t addrW2l = smem_u32(sW2l) + bOff;
    const uint32_t MT = 16 * APAD * 2;
    const uint32_t JT = 8 * APAD * 2;

    float acc[2][8][4];
    #pragma unroll
    for (int i = 0; i < 2; ++i)
        #pragma unroll
        for (int j = 0; j < 8; ++j)
            #pragma unroll
            for (int q = 0; q < 4; ++q) acc[i][j][q] = 0.f;

    for (int kt = 0; kt < D0; kt += 16) {
        // ---- stage A variants (+ stream ego to out[:, 0:768]) ----
        {
            float4 sa, sb, ea, eb;
            if (mOk) {
                sa = __ldg((const float4*)(sideRow + kt));
                sb = __ldg((const float4*)(sideRow + kt + 4));
                ea = __ldg((const float4*)(egoRow + kt));
                eb = __ldg((const float4*)(egoRow + kt + 4));
                *(float4*)(outRow + kt) = ea;
                *(float4*)(outRow + kt + 4) = eb;
            } else {
                sa = make_float4(0.f, 0.f, 0.f, 0.f);
                sb = sa; ea = sa; eb = sa;
            }
            float av[8] = {sa.x + ea.x, sa.y + ea.y, sa.z + ea.z, sa.w + ea.w,
                           sb.x + eb.x, sb.y + eb.y, sb.z + eb.z, sb.w + eb.w};
            float hv[8] = {sa.x * ea.x, sa.y * ea.y, sa.z * ea.z, sa.w * ea.w,
                           sb.x * eb.x, sb.y * eb.y, sb.z * eb.z, sb.w * eb.w};
            uint4 uahi, ualo, uhhi, uhlo;
            uint32_t* pa = (uint32_t*)&uahi; uint32_t* pl = (uint32_t*)&ualo;
            uint32_t* ph = (uint32_t*)&uhhi; uint32_t* pm = (uint32_t*)&uhlo;
            __nv_bfloat16 h0, l0, h1, l1;
            #pragma unroll
            for (int q = 0; q < 4; ++q) {
                split_bf16(av[2 * q], h0, l0);
                split_bf16(av[2 * q + 1], h1, l1);
                pa[q] = pack_bf16(h0, h1);
                pl[q] = pack_bf16(l0, l1);
                split_bf16(hv[2 * q], h0, l0);
                split_bf16(hv[2 * q + 1], h1, l1);
                ph[q] = pack_bf16(h0, h1);
                pm[q] = pack_bf16(l0, l1);
            }
            int d = arow * APAD + akq;
            *(uint4*)(sAhi + d) = uahi;
            *(uint4*)(sAlo + d) = ualo;
            *(uint4*)(sHhi + d) = uhhi;
            *(uint4*)(sHlo + d) = uhlo;
        }
        // ---- stage W planes (one slot per thread) ----
        {
            size_t src = (size_t)wn_row * D0 + kt + wkq;
            int d = wn_row * APAD + wkq;
            *(uint4*)(sW1h + d) = __ldg((const uint4*)(g_w1hiT + src));
            *(uint4*)(sW1l + d) = __ldg((const uint4*)(g_w1loT + src));
            *(uint4*)(sW2h + d) = __ldg((const uint4*)(g_w2hiT + src));
            *(uint4*)(sW2l + d) = __ldg((const uint4*)(g_w2loT + src));
        }
        __syncthreads();

        uint32_t fAhi[2][4], fAlo[2][4], fHhi[2][4], fHlo[2][4];
        ldsm_x4(fAhi[0], addrAhi);       ldsm_x4(fAhi[1], addrAhi + MT);
        ldsm_x4(fAlo[0], addrAlo);       ldsm_x4(fAlo[1], addrAlo + MT);
        ldsm_x4(fHhi[0], addrHhi);       ldsm_x4(fHhi[1], addrHhi + MT);
        ldsm_x4(fHlo[0], addrHlo);       ldsm_x4(fHlo[1], addrHlo + MT);

        #pragma unroll
        for (int j = 0; j < 8; ++j) {
            uint32_t b[2];
            ldsm_x2(b, addrW1h + j * JT);
            mma_bf16(acc[0][j], fAhi[0], b);
            mma_bf16(acc[1][j], fAhi[1], b);
            mma_bf16(acc[0][j], fAlo[0], b);
            mma_bf16(acc[1][j], fAlo[1], b);
            ldsm_x2(b, addrW1l + j * JT);
            mma_bf16(acc[0][j], fAhi[0], b);
            mma_bf16(acc[1][j], fAhi[1], b);
            ldsm_x2(b, addrW2h + j * JT);
            mma_bf16(acc[0][j], fHhi[0], b);
            mma_bf16(acc[1][j], fHhi[1], b);
            mma_bf16(acc[0][j], fHlo[0], b);
            mma_bf16(acc[1][j], fHlo[1], b);
            ldsm_x2(b, addrW2l + j * JT);
            mma_bf16(acc[0][j], fHhi[0], b);
            mma_bf16(acc[1][j], fHhi[1], b);
        }
        __syncthreads();
    }

    // ---- epilogue: bias + leaky, row sum-of-squares ----
    float vals[2][8][4];
    #pragma unroll
    for (int mt = 0; mt < 2; ++mt) {
        float s0 = 0.f, s1 = 0.f;
        #pragma unroll
        for (int j = 0; j < 8; ++j) {
            int col = wn * 64 + j * 8 + (lane & 3) * 2;
            float bc0 = bsum[col], bc1 = bsum[col + 1];
            float v0 = leaky(acc[mt][j][0] + bc0);
            float v1 = leaky(acc[mt][j][1] + bc1);
            float v2 = leaky(acc[mt][j][2] + bc0);
            float v3 = leaky(acc[mt][j][3] + bc1);
            vals[mt][j][0] = v0; vals[mt][j][1] = v1;
            vals[mt][j][2] = v2; vals[mt][j][3] = v3;
            s0 += v0 * v0 + v1 * v1;
            s1 += v2 * v2 + v3 * v3;
        }
        int lr0 = wm * 32 + mt * 16 + (lane >> 2);
        atomicAdd(&rowss[lr0], s0);
        atomicAdd(&rowss[lr0 + 8], s1);
    }
    __syncthreads();

    // ---- write raw ego1 + normalized out[:, 768:896] ----
    #pragma unroll
    for (int mt = 0; mt < 2; ++mt) {
        int lr0 = wm * 32 + mt * 16 + (lane >> 2);
        int row0 = rm + lr0;
        int row1 = row0 + 8;
        float inv0 = 1.f / fmaxf(sqrtf(rowss[lr0]), 1e-12f);
        float inv1 = 1.f / fmaxf(sqrtf(rowss[lr0 + 8]), 1e-12f);
        #pragma unroll
        for (int j = 0; j < 8; ++j) {
            int col = wn * 64 + j * 8 + (lane & 3) * 2;
            if (row0 < NNODES) {
                float2 o = make_float2(vals[mt][j][0], vals[mt][j][1]);
                *(float2*)(g_ego1 + (size_t)row0 * D1 + col) = o;
                float2 n = make_float2(o.x * inv0, o.y * inv0);
                *(float2*)(out + (size_t)row0 * OUTW + D0 + col) = n;
            }
            if (row1 < NNODES) {
                float2 o = make_float2(vals[mt][j][2], vals[mt][j][3]);
                *(float2*)(g_ego1 + (size_t)row1 * D1 + col) = o;
                float2 n = make_float2(o.x * inv1, o.y * inv1);
                *(float2*)(out + (size_t)row1 * OUTW + D0 + col) = n;
            }
        }
    }
}

// ---------------- SpMM layer1: side1 = A @ ego1 (unroll 4) ----------------
__global__ void spmm1_kernel() {
    int w = threadIdx.x >> 5;
    int lane = threadIdx.x & 31;
    int r = blockIdx.x * 4 + w;
    if (r >= NNODES) return;
    int e0 = g_rowptr[r], e1 = g_rowptr[r + 1];
    float4 acc = make_float4(0.f, 0.f, 0.f, 0.f);
    int e = e0;
    int n4 = e0 + ((e1 - e0) & ~3);
    for (; e < n4; e += 4) {
        int c0 = g_col_sorted[e + 0], c1 = g_col_sorted[e + 1];
        int c2 = g_col_sorted[e + 2], c3 = g_col_sorted[e + 3];
        float v0 = g_val_sorted[e + 0], v1 = g_val_sorted[e + 1];
        float v2 = g_val_sorted[e + 2], v3 = g_val_sorted[e + 3];
        float4 x0 = __ldg((const float4*)g_ego1 + (size_t)c0 * (D1 / 4) + lane);
        float4 x1 = __ldg((const float4*)g_ego1 + (size_t)c1 * (D1 / 4) + lane);
        float4 x2 = __ldg((const float4*)g_ego1 + (size_t)c2 * (D1 / 4) + lane);
        float4 x3 = __ldg((const float4*)g_ego1 + (size_t)c3 * (D1 / 4) + lane);
        acc.x += v0 * x0.x + v1 * x1.x + v2 * x2.x + v3 * x3.x;
        acc.y += v0 * x0.y + v1 * x1.y + v2 * x2.y + v3 * x3.y;
        acc.z += v0 * x0.z + v1 * x1.z + v2 * x2.z + v3 * x3.z;
        acc.w += v0 * x0.w + v1 * x1.w + v2 * x2.w + v3 * x3.w;
    }
    for (; e < e1; ++e) {
        int   c = g_col_sorted[e];
        float v = g_val_sorted[e];
        float4 x = __ldg((const float4*)g_ego1 + (size_t)c * (D1 / 4) + lane);
        acc.x += v * x.x; acc.y += v * x.y; acc.z += v * x.z; acc.w += v * x.w;
    }
    ((float4*)g_side1)[(size_t)r * (D1 / 4) + lane] = acc;
}

// ---------------- fused GEMM layer1 + normalize -> out[:, 896:960] ----------------
__global__ __launch_bounds__(256) void gemm1_kernel(
    const float* __restrict__ W1, const float* __restrict__ b1,
    const float* __restrict__ W2, const float* __restrict__ b2,
    float* __restrict__ out) {
    __shared__ __align__(16) float As[16][68];
    __shared__ __align__(16) float Hs[16][68];
    __shared__ __align__(16) float W1s[16][64];
    __shared__ __align__(16) float W2s[16][64];

    int t  = threadIdx.x;
    int tx = t & 31, ty = t >> 5;
    int rm = blockIdx.x * 64;

    float acc[8][2];
    #pragma unroll
    for (int i = 0; i < 8; ++i) { acc[i][0] = 0.f; acc[i][1] = 0.f; }

    int ml = t >> 2;
    int kl = (t & 3) * 4;
    int gm = rm + ml;
    bool mOk = gm < NNODES;
    int wk = t >> 4;
    int wj = (t & 15) * 4;

    for (int kt = 0; kt < D1; kt += 16) {
        if (mOk) {
            float4 s4 = *(const float4*)(g_side1 + (size_t)gm * D1 + kt + kl);
            float4 e4 = *(const float4*)(g_ego1  + (size_t)gm * D1 + kt + kl);
            As[kl + 0][ml] = s4.x + e4.x;  Hs[kl + 0][ml] = s4.x * e4.x;
            As[kl + 1][ml] = s4.y + e4.y;  Hs[kl + 1][ml] = s4.y * e4.y;
            As[kl + 2][ml] = s4.z + e4.z;  Hs[kl + 2][ml] = s4.z * e4.z;
            As[kl + 3][ml] = s4.w + e4.w;  Hs[kl + 3][ml] = s4.w * e4.w;
        } else {
            As[kl + 0][ml] = 0.f; Hs[kl + 0][ml] = 0.f;
            As[kl + 1][ml] = 0.f; Hs[kl + 1][ml] = 0.f;
            As[kl + 2][ml] = 0.f; Hs[kl + 2][ml] = 0.f;
            As[kl + 3][ml] = 0.f; Hs[kl + 3][ml] = 0.f;
        }
        *(float4*)&W1s[wk][wj] = *(const float4*)(W1 + (size_t)(kt + wk) * D2 + wj);
        *(float4*)&W2s[wk][wj] = *(const float4*)(W2 + (size_t)(kt + wk) * D2 + wj);
        __syncthreads();

        #pragma unroll
        for (int k = 0; k < 16; ++k) {
            float2 w1 = *(const float2*)&W1s[k][tx * 2];
            float2 w2 = *(const float2*)&W2s[k][tx * 2];
            float4 a0 = *(const float4*)&As[k][ty * 8];
            float4 a1 = *(const float4*)&As[k][ty * 8 + 4];
            float4 h0 = *(const float4*)&Hs[k][ty * 8];
            float4 h1 = *(const float4*)&Hs[k][ty * 8 + 4];
            float a[8] = {a0.x, a0.y, a0.z, a0.w, a1.x, a1.y, a1.z, a1.w};
            float h[8] = {h0.x, h0.y, h0.z, h0.w, h1.x, h1.y, h1.z, h1.w};
            #pragma unroll
            for (int i = 0; i < 8; ++i) {
                acc[i][0] += a[i] * w1.x + h[i] * w2.x;
                acc[i][1] += a[i] * w1.y + h[i] * w2.y;
            }
        }
        __syncthreads();
    }

    int jc = tx * 2;
    float bs0 = b1[jc] + b2[jc];
    float bs1 = b1[jc + 1] + b2[jc + 1];
    #pragma unroll
    for (int i = 0; i < 8; ++i) {
        int row = rm + ty * 8 + i;
        float v0 = leaky(acc[i][0] + bs0);
        float v1 = leaky(acc[i][1] + bs1);
        float ss = v0 * v0 + v1 * v1;
        #pragma unroll
        for (int off = 16; off > 0; off >>= 1)
            ss += __shfl_xor_sync(0xffffffffu, ss, off);
        float inv = 1.f / fmaxf(sqrtf(ss), 1e-12f);
        if (row < NNODES) {
            float2 o = make_float2(v0 * inv, v1 * inv);
            *(float2*)(out + (size_t)row * OUTW + (D0 + D1) + jc) = o;
        }
    }
}

// ---------------- launch ----------------
extern "C" void kernel_launch(void* const* d_in, const int* in_sizes, int n_in,
                              void* d_out, int out_size) {
    const float* item  = (const float*)d_in[0];
    const float* user  = (const float*)d_in[1];
    const float* W1_0  = (const float*)d_in[2];
    const float* b1_0  = (const float*)d_in[3];
    const float* W2_0  = (const float*)d_in[4];
    const float* b2_0  = (const float*)d_in[5];
    const float* W1_1  = (const float*)d_in[6];
    const float* b1_1  = (const float*)d_in[7];
    const float* W2_1  = (const float*)d_in[8];
    const float* b2_1  = (const float*)d_in[9];
    const float* evals = (const float*)d_in[10];
    const int*   erows = (const int*)d_in[11];
    const int*   ecols = (const int*)d_in[12];
    float* out = (float*)d_out;

    // idempotent; safe under capture (not a stream op / allocation)
    cudaFuncSetAttribute(gemm0_mma_kernel,
                         cudaFuncAttributeMaxDynamicSharedMemorySize, GEMM0_SMEM);

    init_hist_kernel<<<64, 256>>>();
    hist_kernel<<<(NEDGES + 255) / 256, 256>>>(erows);
    scan_local_kernel<<<SCANB, 1024>>>();
    scan_bsum_kernel<<<1, 64>>>();
    scan_add_kernel<<<SCANB, 1024>>>();
    scatter_kernel<<<(NEDGES + 255) / 256, 256>>>(erows, ecols, evals);
    wsplit_kernel<<<(D1 * D0 + 255) / 256, 256>>>(W1_0, W2_0);

    {
        dim3 grid((NNODES + 7) / 8, D0 / 128);   // y = feature chunk (slow dim)
        spmm0_chunk_kernel<<<grid, 256>>>(item, user);
    }
    gemm0_mma_kernel<<<(NNODES + 127) / 128, 256, GEMM0_SMEM>>>(item, user, b1_0, b2_0, out);
    spmm1_kernel<<<(NNODES + 3) / 4, 128>>>();
    gemm1_kernel<<<(NNODES + 63) / 64, 256>>>(W1_1, b1_1, W2_1, b2_1, out);
}

// round 13
// speedup vs baseline: 1.0434x; 1.0434x over previous
#include <cuda_runtime.h>
#include <cuda_bf16.h>
#include <cstdint>

#define N_ITEMS 30000
#define N_USERS 20000
#define NNODES  50000
#define NEDGES  512000
#define D0 768
#define D1 128
#define D2 64
#define OUTW 960   // 768 + 128 + 64
#define SCANB ((NNODES + 1023) / 1024)   // 49

// ---------------- device scratch (static, no runtime alloc) ----------------
__device__ float g_side0[(size_t)NNODES * D0];   // 153.6 MB
__device__ float g_ego1 [(size_t)NNODES * D1];   // 25.6 MB
__device__ float g_side1[(size_t)NNODES * D1];   // 25.6 MB
__device__ int   g_hist[NNODES];
__device__ int   g_rowptr[NNODES + 1];
__device__ int   g_cursor[NNODES];
__device__ int   g_col_sorted[NEDGES];
__device__ float g_val_sorted[NEDGES];
__device__ int   g_bsum[64];
__device__ int   g_boff[64];
// split + transposed weights for tensor-core gemm0: [N=128][K=768] bf16
__device__ __nv_bfloat16 g_w1hiT[D1 * D0];
__device__ __nv_bfloat16 g_w1loT[D1 * D0];
__device__ __nv_bfloat16 g_w2hiT[D1 * D0];
__device__ __nv_bfloat16 g_w2loT[D1 * D0];

__device__ __forceinline__ float leaky(float v) { return v > 0.f ? v : 0.01f * v; }

__device__ __forceinline__ uint32_t smem_u32(const void* p) {
    uint32_t a;
    asm("{ .reg .u64 t; cvta.to.shared.u64 t, %1; cvt.u32.u64 %0, t; }"
        : "=r"(a) : "l"(p));
    return a;
}
__device__ __forceinline__ void ldsm_x4(uint32_t* r, uint32_t addr) {
    asm volatile("ldmatrix.sync.aligned.m8n8.x4.shared.b16 {%0,%1,%2,%3}, [%4];"
                 : "=r"(r[0]), "=r"(r[1]), "=r"(r[2]), "=r"(r[3]) : "r"(addr));
}
__device__ __forceinline__ void mma_bf16(float* d, const uint32_t* a, const uint32_t* b) {
    asm volatile(
        "mma.sync.aligned.m16n8k16.row.col.f32.bf16.bf16.f32 "
        "{%0,%1,%2,%3}, {%4,%5,%6,%7}, {%8,%9}, {%0,%1,%2,%3};"
        : "+f"(d[0]), "+f"(d[1]), "+f"(d[2]), "+f"(d[3])
        : "r"(a[0]), "r"(a[1]), "r"(a[2]), "r"(a[3]), "r"(b[0]), "r"(b[1]));
}
__device__ __forceinline__ uint32_t pack_bf16(__nv_bfloat16 a, __nv_bfloat16 b) {
    return ((uint32_t)__bfloat16_as_ushort(b) << 16) | (uint32_t)__bfloat16_as_ushort(a);
}
__device__ __forceinline__ void split_bf16(float x, __nv_bfloat16& hi, __nv_bfloat16& lo) {
    hi = __float2bfloat16(x);
    lo = __float2bfloat16(x - __bfloat162float(hi));
}

// ---------------- CSR build ----------------
__global__ void init_hist_kernel() {
    for (int i = blockIdx.x * blockDim.x + threadIdx.x; i < NNODES;
         i += gridDim.x * blockDim.x)
        g_hist[i] = 0;
}

__global__ void hist_kernel(const int* __restrict__ rows) {
    int e = blockIdx.x * blockDim.x + threadIdx.x;
    if (e < NEDGES) atomicAdd(&g_hist[rows[e]], 1);
}

__global__ void scan_local_kernel() {
    __shared__ int wsum[32];
    int tid = threadIdx.x, lane = tid & 31, wid = tid >> 5;
    int i = blockIdx.x * 1024 + tid;
    int v = (i < NNODES) ? g_hist[i] : 0;
    int x = v;
    #pragma unroll
    for (int off = 1; off < 32; off <<= 1) {
        int t = __shfl_up_sync(0xffffffffu, x, off);
        if (lane >= off) x += t;
    }
    if (lane == 31) wsum[wid] = x;
    __syncthreads();
    if (wid == 0) {
        int w = wsum[lane];
        #pragma unroll
        for (int off = 1; off < 32; off <<= 1) {
            int t = __shfl_up_sync(0xffffffffu, w, off);
            if (lane >= off) w += t;
        }
        wsum[lane] = w;
    }
    __syncthreads();
    int warp_off = (wid == 0) ? 0 : wsum[wid - 1];
    int incl = x + warp_off;
    if (i < NNODES) g_rowptr[i] = incl - v;
    if (tid == 1023) g_bsum[blockIdx.x] = incl;
}

__global__ void scan_bsum_kernel() {   // 1 block, 64 threads
    __shared__ int s[64];
    int tid = threadIdx.x;
    int v = (tid < SCANB) ? g_bsum[tid] : 0;
    s[tid] = v;
    __syncthreads();
    #pragma unroll
    for (int off = 1; off < 64; off <<= 1) {
        int t = (tid >= off) ? s[tid - off] : 0;
        __syncthreads();
        s[tid] += t;
        __syncthreads();
    }
    g_boff[tid] = s[tid] - v;
    if (tid == SCANB - 1) g_rowptr[NNODES] = s[tid];
}

__global__ void scan_add_kernel() {
    int i = blockIdx.x * 1024 + threadIdx.x;
    if (i < NNODES) {
        int val = g_rowptr[i] + g_boff[blockIdx.x];
        g_rowptr[i] = val;
        g_cursor[i] = val;
    }
}

__global__ void scatter_kernel(const int* __restrict__ rows,
                               const int* __restrict__ cols,
                               const float* __restrict__ vals) {
    int e = blockIdx.x * blockDim.x + threadIdx.x;
    if (e < NEDGES) {
        int r = rows[e];
        int p = atomicAdd(&g_cursor[r], 1);
        g_col_sorted[p] = cols[e];
        g_val_sorted[p] = vals[e];
    }
}

// ---------------- W split+transpose prep ----------------
__global__ void wsplit_kernel(const float* __restrict__ W1,
                              const float* __restrict__ W2) {
    int idx = blockIdx.x * blockDim.x + threadIdx.x;
    if (idx >= D1 * D0) return;
    int n = idx / D0, k = idx - n * D0;
    float w1 = W1[(size_t)k * D1 + n];
    float w2 = W2[(size_t)k * D1 + n];
    __nv_bfloat16 hi, lo;
    split_bf16(w1, hi, lo);
    g_w1hiT[idx] = hi; g_w1loT[idx] = lo;
    split_bf16(w2, hi, lo);
    g_w2hiT[idx] = hi; g_w2loT[idx] = lo;
}

// ---------------- SpMM layer0 (128-wide chunks, unroll 8) ----------------
__global__ __launch_bounds__(256) void spmm0_chunk_kernel(
    const float* __restrict__ item, const float* __restrict__ user) {
    const int w = threadIdx.x >> 5;      // warp -> row
    const int lane = threadIdx.x & 31;   // lane -> 4 cols
    const int r = blockIdx.x * 8 + w;
    const int off = blockIdx.y * 128 + lane * 4;
    if (r >= NNODES) return;
    const int e0 = g_rowptr[r], e1 = g_rowptr[r + 1];
    float4 acc = make_float4(0.f, 0.f, 0.f, 0.f);
    int e = e0;
    const int n8 = e0 + ((e1 - e0) & ~7);
    for (; e < n8; e += 8) {
        const float* p[8];
        float v[8];
        #pragma unroll
        for (int q = 0; q < 8; ++q) {
            int c = g_col_sorted[e + q];
            v[q] = g_val_sorted[e + q];
            p[q] = ((c < N_ITEMS) ? item + (size_t)c * D0
                                  : user + (size_t)(c - N_ITEMS) * D0) + off;
        }
        float4 x[8];
        #pragma unroll
        for (int q = 0; q < 8; ++q) x[q] = __ldg((const float4*)p[q]);
        #pragma unroll
        for (int q = 0; q < 8; ++q) {
            acc.x += v[q] * x[q].x;
            acc.y += v[q] * x[q].y;
            acc.z += v[q] * x[q].z;
            acc.w += v[q] * x[q].w;
        }
    }
    for (; e < e1; ++e) {
        int   c = g_col_sorted[e];
        float v = g_val_sorted[e];
        const float* p = ((c < N_ITEMS) ? item + (size_t)c * D0
                                        : user + (size_t)(c - N_ITEMS) * D0) + off;
        float4 x = __ldg((const float4*)p);
        acc.x += v * x.x; acc.y += v * x.y; acc.z += v * x.z; acc.w += v * x.w;
    }
    *(float4*)(g_side0 + (size_t)r * D0 + off) = acc;
}

// ---------------- fused GEMM layer0 (mma.sync bf16, 3-term split) ----------------
// ego1 = leaky((side0+ego0)@W1 + b1 + (side0*ego0)@W2 + b2)
// Streams ego0 -> out[:, 0:768]; fuses row-normalize -> out[:, 768:896].
// BM=64, BN=128, BK=16, 128 threads (4 warps 2x2, warp tile 32x64).
// B fragments loaded via ldmatrix.x4 over j-pairs (24 LDSM/k16 vs 40).
#define APAD 24   // row stride in bf16 (48 B, conflict-free ldmatrix)

__global__ __launch_bounds__(128) void gemm0_mma_kernel(
    const float* __restrict__ item, const float* __restrict__ user,
    const float* __restrict__ b1, const float* __restrict__ b2,
    float* __restrict__ out) {
    __shared__ __align__(16) __nv_bfloat16 sAhi[64 * APAD];
    __shared__ __align__(16) __nv_bfloat16 sAlo[64 * APAD];
    __shared__ __align__(16) __nv_bfloat16 sHhi[64 * APAD];
    __shared__ __align__(16) __nv_bfloat16 sHlo[64 * APAD];
    __shared__ __align__(16) __nv_bfloat16 sW1h[128 * APAD];
    __shared__ __align__(16) __nv_bfloat16 sW1l[128 * APAD];
    __shared__ __align__(16) __nv_bfloat16 sW2h[128 * APAD];
    __shared__ __align__(16) __nv_bfloat16 sW2l[128 * APAD];
    __shared__ float bsum[D1];
    __shared__ float rowss[64];

    const int t    = threadIdx.x;
    const int lane = t & 31;
    const int wid  = t >> 5;
    const int wm   = wid >> 1;
    const int wn   = wid & 1;
    const int rm   = blockIdx.x * 64;

    bsum[t] = b1[t] + b2[t];
    if (t < 64) rowss[t] = 0.f;

    const int arow = t >> 1;
    const int akq  = (t & 1) * 8;
    const int gm   = rm + arow;
    const bool mOk = gm < NNODES;
    const float* sideRow = g_side0 + (size_t)gm * D0 + akq;
    const float* egoRow  = ((gm < N_ITEMS) ? item + (size_t)gm * D0
                                           : user + (size_t)(gm - N_ITEMS) * D0) + akq;
    float* outRow = out + (size_t)gm * OUTW + akq;

    // A ldmatrix addresses (x4: 16 rows x 16 k per call)
    const uint32_t aOff = (uint32_t)(((wm * 32 + (lane & 15)) * APAD + (lane >> 4) * 8) * 2);
    const uint32_t addrAhi = smem_u32(sAhi) + aOff;
    const uint32_t addrAlo = smem_u32(sAlo) + aOff;
    const uint32_t addrHhi = smem_u32(sHhi) + aOff;
    const uint32_t addrHlo = smem_u32(sHlo) + aOff;
    // B ldmatrix.x4 address: tiles (n0,k0),(n0,k8),(n0+8,k0),(n0+8,k8)
    // lane&7 -> row within 8; bit3 -> k8; bit4 -> +8 n
    const uint32_t bOff4 = (uint32_t)(((wn * 64 + (lane & 7) + ((lane >> 4) << 3)) * APAD
                                       + ((lane >> 3) & 1) * 8) * 2);
    const uint32_t addrW1h = smem_u32(sW1h) + bOff4;
    const uint32_t addrW1l = smem_u32(sW1l) + bOff4;
    const uint32_t addrW2h = smem_u32(sW2h) + bOff4;
    const uint32_t addrW2l = smem_u32(sW2l) + bOff4;
    const uint32_t MT  = 16 * APAD * 2;   // A m-tile stride (bytes)
    const uint32_t J2T = 16 * APAD * 2;   // B j-pair stride (16 n rows)

    float acc[2][8][4];
    #pragma unroll
    for (int i = 0; i < 2; ++i)
        #pragma unroll
        for (int j = 0; j < 8; ++j)
            #pragma unroll
            for (int q = 0; q < 4; ++q) acc[i][j][q] = 0.f;

    for (int kt = 0; kt < D0; kt += 16) {
        // ---- stage A variants (+ stream ego to out[:, 0:768]) ----
        {
            float4 sa, sb, ea, eb;
            if (mOk) {
                sa = __ldg((const float4*)(sideRow + kt));
                sb = __ldg((const float4*)(sideRow + kt + 4));
                ea = __ldg((const float4*)(egoRow + kt));
                eb = __ldg((const float4*)(egoRow + kt + 4));
                *(float4*)(outRow + kt) = ea;
                *(float4*)(outRow + kt + 4) = eb;
            } else {
                sa = make_float4(0.f, 0.f, 0.f, 0.f);
                sb = sa; ea = sa; eb = sa;
            }
            float av[8] = {sa.x + ea.x, sa.y + ea.y, sa.z + ea.z, sa.w + ea.w,
                           sb.x + eb.x, sb.y + eb.y, sb.z + eb.z, sb.w + eb.w};
            float hv[8] = {sa.x * ea.x, sa.y * ea.y, sa.z * ea.z, sa.w * ea.w,
                           sb.x * eb.x, sb.y * eb.y, sb.z * eb.z, sb.w * eb.w};
            uint4 uahi, ualo, uhhi, uhlo;
            uint32_t* pa = (uint32_t*)&uahi; uint32_t* pl = (uint32_t*)&ualo;
            uint32_t* ph = (uint32_t*)&uhhi; uint32_t* pm = (uint32_t*)&uhlo;
            __nv_bfloat16 h0, l0, h1, l1;
            #pragma unroll
            for (int q = 0; q < 4; ++q) {
                split_bf16(av[2 * q], h0, l0);
                split_bf16(av[2 * q + 1], h1, l1);
                pa[q] = pack_bf16(h0, h1);
                pl[q] = pack_bf16(l0, l1);
                split_bf16(hv[2 * q], h0, l0);
                split_bf16(hv[2 * q + 1], h1, l1);
                ph[q] = pack_bf16(h0, h1);
                pm[q] = pack_bf16(l0, l1);
            }
            int d = arow * APAD + akq;
            *(uint4*)(sAhi + d) = uahi;
            *(uint4*)(sAlo + d) = ualo;
            *(uint4*)(sHhi + d) = uhhi;
            *(uint4*)(sHlo + d) = uhlo;
        }
        // ---- stage W planes ----
        #pragma unroll
        for (int s = 0; s < 2; ++s) {
            int g = s * 128 + t;
            int n = g >> 1;
            int kq = (g & 1) * 8;
            size_t src = (size_t)n * D0 + kt + kq;
            int d = n * APAD + kq;
            *(uint4*)(sW1h + d) = __ldg((const uint4*)(g_w1hiT + src));
            *(uint4*)(sW1l + d) = __ldg((const uint4*)(g_w1loT + src));
            *(uint4*)(sW2h + d) = __ldg((const uint4*)(g_w2hiT + src));
            *(uint4*)(sW2l + d) = __ldg((const uint4*)(g_w2loT + src));
        }
        __syncthreads();

        // ---- A fragments (4 variants x 2 m-tiles) ----
        uint32_t fAhi[2][4], fAlo[2][4], fHhi[2][4], fHlo[2][4];
        ldsm_x4(fAhi[0], addrAhi);       ldsm_x4(fAhi[1], addrAhi + MT);
        ldsm_x4(fAlo[0], addrAlo);       ldsm_x4(fAlo[1], addrAlo + MT);
        ldsm_x4(fHhi[0], addrHhi);       ldsm_x4(fHhi[1], addrHhi + MT);
        ldsm_x4(fHlo[0], addrHlo);       ldsm_x4(fHlo[1], addrHlo + MT);

        // ---- B fragments via x4 over j-pairs; 24 mma per pair ----
        #pragma unroll
        for (int jj = 0; jj < 4; ++jj) {
            const int j0 = 2 * jj, j1 = 2 * jj + 1;
            uint32_t b1h[4], b1l[4], b2h[4], b2l[4];
            ldsm_x4(b1h, addrW1h + jj * J2T);
            ldsm_x4(b1l, addrW1l + jj * J2T);
            ldsm_x4(b2h, addrW2h + jj * J2T);
            ldsm_x4(b2l, addrW2l + jj * J2T);
            // A @ W1: hi*hi, hi*lo, lo*hi
            mma_bf16(acc[0][j0], fAhi[0], b1h);
            mma_bf16(acc[1][j0], fAhi[1], b1h);
            mma_bf16(acc[0][j1], fAhi[0], b1h + 2);
            mma_bf16(acc[1][j1], fAhi[1], b1h + 2);
            mma_bf16(acc[0][j0], fAlo[0], b1h);
            mma_bf16(acc[1][j0], fAlo[1], b1h);
            mma_bf16(acc[0][j1], fAlo[0], b1h + 2);
            mma_bf16(acc[1][j1], fAlo[1], b1h + 2);
            mma_bf16(acc[0][j0], fAhi[0], b1l);
            mma_bf16(acc[1][j0], fAhi[1], b1l);
            mma_bf16(acc[0][j1], fAhi[0], b1l + 2);
            mma_bf16(acc[1][j1], fAhi[1], b1l + 2);
            // H @ W2: hi*hi, hi*lo, lo*hi
            mma_bf16(acc[0][j0], fHhi[0], b2h);
            mma_bf16(acc[1][j0], fHhi[1], b2h);
            mma_bf16(acc[0][j1], fHhi[0], b2h + 2);
            mma_bf16(acc[1][j1], fHhi[1], b2h + 2);
            mma_bf16(acc[0][j0], fHlo[0], b2h);
            mma_bf16(acc[1][j0], fHlo[1], b2h);
            mma_bf16(acc[0][j1], fHlo[0], b2h + 2);
            mma_bf16(acc[1][j1], fHlo[1], b2h + 2);
            mma_bf16(acc[0][j0], fHhi[0], b2l);
            mma_bf16(acc[1][j0], fHhi[1], b2l);
            mma_bf16(acc[0][j1], fHhi[0], b2l + 2);
            mma_bf16(acc[1][j1], fHhi[1], b2l + 2);
        }
        __syncthreads();
    }

    // ---- epilogue: bias + leaky, row sum-of-squares ----
    float vals[2][8][4];
    #pragma unroll
    for (int mt = 0; mt < 2; ++mt) {
        float s0 = 0.f, s1 = 0.f;
        #pragma unroll
        for (int j = 0; j < 8; ++j) {
            int col = wn * 64 + j * 8 + (lane & 3) * 2;
            float bc0 = bsum[col], bc1 = bsum[col + 1];
            float v0 = leaky(acc[mt][j][0] + bc0);
            float v1 = leaky(acc[mt][j][1] + bc1);
            float v2 = leaky(acc[mt][j][2] + bc0);
            float v3 = leaky(acc[mt][j][3] + bc1);
            vals[mt][j][0] = v0; vals[mt][j][1] = v1;
            vals[mt][j][2] = v2; vals[mt][j][3] = v3;
            s0 += v0 * v0 + v1 * v1;
            s1 += v2 * v2 + v3 * v3;
        }
        int lr0 = wm * 32 + mt * 16 + (lane >> 2);
        atomicAdd(&rowss[lr0], s0);
        atomicAdd(&rowss[lr0 + 8], s1);
    }
    __syncthreads();

    // ---- write raw ego1 + normalized out[:, 768:896] ----
    #pragma unroll
    for (int mt = 0; mt < 2; ++mt) {
        int lr0 = wm * 32 + mt * 16 + (lane >> 2);
        int row0 = rm + lr0;
        int row1 = row0 + 8;
        float inv0 = 1.f / fmaxf(sqrtf(rowss[lr0]), 1e-12f);
        float inv1 = 1.f / fmaxf(sqrtf(rowss[lr0 + 8]), 1e-12f);
        #pragma unroll
        for (int j = 0; j < 8; ++j) {
            int col = wn * 64 + j * 8 + (lane & 3) * 2;
            if (row0 < NNODES) {
                float2 o = make_float2(vals[mt][j][0], vals[mt][j][1]);
                *(float2*)(g_ego1 + (size_t)row0 * D1 + col) = o;
                float2 n = make_float2(o.x * inv0, o.y * inv0);
                *(float2*)(out + (size_t)row0 * OUTW + D0 + col) = n;
            }
            if (row1 < NNODES) {
                float2 o = make_float2(vals[mt][j][2], vals[mt][j][3]);
                *(float2*)(g_ego1 + (size_t)row1 * D1 + col) = o;
                float2 n = make_float2(o.x * inv1, o.y * inv1);
                *(float2*)(out + (size_t)row1 * OUTW + D0 + col) = n;
            }
        }
    }
}

// ---------------- SpMM layer1: side1 = A @ ego1 (unroll 4) ----------------
__global__ void spmm1_kernel() {
    int w = threadIdx.x >> 5;
    int lane = threadIdx.x & 31;
    int r = blockIdx.x * 4 + w;
    if (r >= NNODES) return;
    int e0 = g_rowptr[r], e1 = g_rowptr[r + 1];
    float4 acc = make_float4(0.f, 0.f, 0.f, 0.f);
    int e = e0;
    int n4 = e0 + ((e1 - e0) & ~3);
    for (; e < n4; e += 4) {
        int c0 = g_col_sorted[e + 0], c1 = g_col_sorted[e + 1];
        int c2 = g_col_sorted[e + 2], c3 = g_col_sorted[e + 3];
        float v0 = g_val_sorted[e + 0], v1 = g_val_sorted[e + 1];
        float v2 = g_val_sorted[e + 2], v3 = g_val_sorted[e + 3];
        float4 x0 = __ldg((const float4*)g_ego1 + (size_t)c0 * (D1 / 4) + lane);
        float4 x1 = __ldg((const float4*)g_ego1 + (size_t)c1 * (D1 / 4) + lane);
        float4 x2 = __ldg((const float4*)g_ego1 + (size_t)c2 * (D1 / 4) + lane);
        float4 x3 = __ldg((const float4*)g_ego1 + (size_t)c3 * (D1 / 4) + lane);
        acc.x += v0 * x0.x + v1 * x1.x + v2 * x2.x + v3 * x3.x;
        acc.y += v0 * x0.y + v1 * x1.y + v2 * x2.y + v3 * x3.y;
        acc.z += v0 * x0.z + v1 * x1.z + v2 * x2.z + v3 * x3.z;
        acc.w += v0 * x0.w + v1 * x1.w + v2 * x2.w + v3 * x3.w;
    }
    for (; e < e1; ++e) {
        int   c = g_col_sorted[e];
        float v = g_val_sorted[e];
        float4 x = __ldg((const float4*)g_ego1 + (size_t)c * (D1 / 4) + lane);
        acc.x += v * x.x; acc.y += v * x.y; acc.z += v * x.z; acc.w += v * x.w;
    }
    ((float4*)g_side1)[(size_t)r * (D1 / 4) + lane] = acc;
}

// ---------------- fused GEMM layer1 + normalize -> out[:, 896:960] ----------------
__global__ __launch_bounds__(256) void gemm1_kernel(
    const float* __restrict__ W1, const float* __restrict__ b1,
    const float* __restrict__ W2, const float* __restrict__ b2,
    float* __restrict__ out) {
    __shared__ __align__(16) float As[16][68];
    __shared__ __align__(16) float Hs[16][68];
    __shared__ __align__(16) float W1s[16][64];
    __shared__ __align__(16) float W2s[16][64];

    int t  = threadIdx.x;
    int tx = t & 31, ty = t >> 5;
    int rm = blockIdx.x * 64;

    float acc[8][2];
    #pragma unroll
    for (int i = 0; i < 8; ++i) { acc[i][0] = 0.f; acc[i][1] = 0.f; }

    int ml = t >> 2;
    int kl = (t & 3) * 4;
    int gm = rm + ml;
    bool mOk = gm < NNODES;
    int wk = t >> 4;
    int wj = (t & 15) * 4;

    for (int kt = 0; kt < D1; kt += 16) {
        if (mOk) {
            float4 s4 = *(const float4*)(g_side1 + (size_t)gm * D1 + kt + kl);
            float4 e4 = *(const float4*)(g_ego1  + (size_t)gm * D1 + kt + kl);
            As[kl + 0][ml] = s4.x + e4.x;  Hs[kl + 0][ml] = s4.x * e4.x;
            As[kl + 1][ml] = s4.y + e4.y;  Hs[kl + 1][ml] = s4.y * e4.y;
            As[kl + 2][ml] = s4.z + e4.z;  Hs[kl + 2][ml] = s4.z * e4.z;
            As[kl + 3][ml] = s4.w + e4.w;  Hs[kl + 3][ml] = s4.w * e4.w;
        } else {
            As[kl + 0][ml] = 0.f; Hs[kl + 0][ml] = 0.f;
            As[kl + 1][ml] = 0.f; Hs[kl + 1][ml] = 0.f;
            As[kl + 2][ml] = 0.f; Hs[kl + 2][ml] = 0.f;
            As[kl + 3][ml] = 0.f; Hs[kl + 3][ml] = 0.f;
        }
        *(float4*)&W1s[wk][wj] = *(const float4*)(W1 + (size_t)(kt + wk) * D2 + wj);
        *(float4*)&W2s[wk][wj] = *(const float4*)(W2 + (size_t)(kt + wk) * D2 + wj);
        __syncthreads();

        #pragma unroll
        for (int k = 0; k < 16; ++k) {
            float2 w1 = *(const float2*)&W1s[k][tx * 2];
            float2 w2 = *(const float2*)&W2s[k][tx * 2];
            float4 a0 = *(const float4*)&As[k][ty * 8];
            float4 a1 = *(const float4*)&As[k][ty * 8 + 4];
            float4 h0 = *(const float4*)&Hs[k][ty * 8];
            float4 h1 = *(const float4*)&Hs[k][ty * 8 + 4];
            float a[8] = {a0.x, a0.y, a0.z, a0.w, a1.x, a1.y, a1.z, a1.w};
            float h[8] = {h0.x, h0.y, h0.z, h0.w, h1.x, h1.y, h1.z, h1.w};
            #pragma unroll
            for (int i = 0; i < 8; ++i) {
                acc[i][0] += a[i] * w1.x + h[i] * w2.x;
                acc[i][1] += a[i] * w1.y + h[i] * w2.y;
            }
        }
        __syncthreads();
    }

    int jc = tx * 2;
    float bs0 = b1[jc] + b2[jc];
    float bs1 = b1[jc + 1] + b2[jc + 1];
    #pragma unroll
    for (int i = 0; i < 8; ++i) {
        int row = rm + ty * 8 + i;
        float v0 = leaky(acc[i][0] + bs0);
        float v1 = leaky(acc[i][1] + bs1);
        float ss = v0 * v0 + v1 * v1;
        #pragma unroll
        for (int off = 16; off > 0; off >>= 1)
            ss += __shfl_xor_sync(0xffffffffu, ss, off);
        float inv = 1.f / fmaxf(sqrtf(ss), 1e-12f);
        if (row < NNODES) {
            float2 o = make_float2(v0 * inv, v1 * inv);
            *(float2*)(out + (size_t)row * OUTW + (D0 + D1) + jc) = o;
        }
    }
}

// ---------------- launch ----------------
extern "C" void kernel_launch(void* const* d_in, const int* in_sizes, int n_in,
                              void* d_out, int out_size) {
    const float* item  = (const float*)d_in[0];
    const float* user  = (const float*)d_in[1];
    const float* W1_0  = (const float*)d_in[2];
    const float* b1_0  = (const float*)d_in[3];
    const float* W2_0  = (const float*)d_in[4];
    const float* b2_0  = (const float*)d_in[5];
    const float* W1_1  = (const float*)d_in[6];
    const float* b1_1  = (const float*)d_in[7];
    const float* W2_1  = (const float*)d_in[8];
    const float* b2_1  = (const float*)d_in[9];
    const float* evals = (const float*)d_in[10];
    const int*   erows = (const int*)d_in[11];
    const int*   ecols = (const int*)d_in[12];
    float* out = (float*)d_out;

    init_hist_kernel<<<64, 256>>>();
    hist_kernel<<<(NEDGES + 255) / 256, 256>>>(erows);
    scan_local_kernel<<<SCANB, 1024>>>();
    scan_bsum_kernel<<<1, 64>>>();
    scan_add_kernel<<<SCANB, 1024>>>();
    scatter_kernel<<<(NEDGES + 255) / 256, 256>>>(erows, ecols, evals);
    wsplit_kernel<<<(D1 * D0 + 255) / 256, 256>>>(W1_0, W2_0);

    {
        dim3 grid((NNODES + 7) / 8, D0 / 128);   // y = feature chunk (slow dim)
        spmm0_chunk_kernel<<<grid, 256>>>(item, user);
    }
    gemm0_mma_kernel<<<(NNODES + 63) / 64, 128>>>(item, user, b1_0, b2_0, out);
    spmm1_kernel<<<(NNODES + 3) / 4, 128>>>();
    gemm1_kernel<<<(NNODES + 63) / 64, 256>>>(W1_1, b1_1, W2_1, b2_1, out);
}

// round 14
// speedup vs baseline: 1.0440x; 1.0006x over previous
#include <cuda_runtime.h>
#include <cuda_bf16.h>
#include <cstdint>

#define N_ITEMS 30000
#define N_USERS 20000
#define NNODES  50000
#define NEDGES  512000
#define D0 768
#define D1 128
#define D2 64
#define OUTW 960   // 768 + 128 + 64
#define SCANB ((NNODES + 1023) / 1024)   // 49

// ---------------- device scratch (static, no runtime alloc) ----------------
__device__ float g_side0[(size_t)NNODES * D0];   // 153.6 MB
__device__ __nv_bfloat16 g_egobf[(size_t)NNODES * D0];  // 76.8 MB (gather source)
__device__ float g_ego1 [(size_t)NNODES * D1];   // 25.6 MB
__device__ float g_side1[(size_t)NNODES * D1];   // 25.6 MB
__device__ int   g_hist[NNODES];
__device__ int   g_rowptr[NNODES + 1];
__device__ int   g_cursor[NNODES];
__device__ int   g_col_sorted[NEDGES];
__device__ float g_val_sorted[NEDGES];
__device__ int   g_bsum[64];
__device__ int   g_boff[64];
// split + transposed weights for tensor-core gemm0: [N=128][K=768] bf16
__device__ __nv_bfloat16 g_w1hiT[D1 * D0];
__device__ __nv_bfloat16 g_w1loT[D1 * D0];
__device__ __nv_bfloat16 g_w2hiT[D1 * D0];
__device__ __nv_bfloat16 g_w2loT[D1 * D0];

__device__ __forceinline__ float leaky(float v) { return v > 0.f ? v : 0.01f * v; }

__device__ __forceinline__ uint32_t smem_u32(const void* p) {
    uint32_t a;
    asm("{ .reg .u64 t; cvta.to.shared.u64 t, %1; cvt.u32.u64 %0, t; }"
        : "=r"(a) : "l"(p));
    return a;
}
__device__ __forceinline__ void ldsm_x4(uint32_t* r, uint32_t addr) {
    asm volatile("ldmatrix.sync.aligned.m8n8.x4.shared.b16 {%0,%1,%2,%3}, [%4];"
                 : "=r"(r[0]), "=r"(r[1]), "=r"(r[2]), "=r"(r[3]) : "r"(addr));
}
__device__ __forceinline__ void mma_bf16(float* d, const uint32_t* a, const uint32_t* b) {
    asm volatile(
        "mma.sync.aligned.m16n8k16.row.col.f32.bf16.bf16.f32 "
        "{%0,%1,%2,%3}, {%4,%5,%6,%7}, {%8,%9}, {%0,%1,%2,%3};"
        : "+f"(d[0]), "+f"(d[1]), "+f"(d[2]), "+f"(d[3])
        : "r"(a[0]), "r"(a[1]), "r"(a[2]), "r"(a[3]), "r"(b[0]), "r"(b[1]));
}
__device__ __forceinline__ uint32_t pack_bf16(__nv_bfloat16 a, __nv_bfloat16 b) {
    return ((uint32_t)__bfloat16_as_ushort(b) << 16) | (uint32_t)__bfloat16_as_ushort(a);
}
__device__ __forceinline__ void split_bf16(float x, __nv_bfloat16& hi, __nv_bfloat16& lo) {
    hi = __float2bfloat16(x);
    lo = __float2bfloat16(x - __bfloat162float(hi));
}

// ---------------- CSR build ----------------
__global__ void init_hist_kernel() {
    for (int i = blockIdx.x * blockDim.x + threadIdx.x; i < NNODES;
         i += gridDim.x * blockDim.x)
        g_hist[i] = 0;
}

__global__ void hist_kernel(const int* __restrict__ rows) {
    int e = blockIdx.x * blockDim.x + threadIdx.x;
    if (e < NEDGES) atomicAdd(&g_hist[rows[e]], 1);
}

__global__ void scan_local_kernel() {
    __shared__ int wsum[32];
    int tid = threadIdx.x, lane = tid & 31, wid = tid >> 5;
    int i = blockIdx.x * 1024 + tid;
    int v = (i < NNODES) ? g_hist[i] : 0;
    int x = v;
    #pragma unroll
    for (int off = 1; off < 32; off <<= 1) {
        int t = __shfl_up_sync(0xffffffffu, x, off);
        if (lane >= off) x += t;
    }
    if (lane == 31) wsum[wid] = x;
    __syncthreads();
    if (wid == 0) {
        int w = wsum[lane];
        #pragma unroll
        for (int off = 1; off < 32; off <<= 1) {
            int t = __shfl_up_sync(0xffffffffu, w, off);
            if (lane >= off) w += t;
        }
        wsum[lane] = w;
    }
    __syncthreads();
    int warp_off = (wid == 0) ? 0 : wsum[wid - 1];
    int incl = x + warp_off;
    if (i < NNODES) g_rowptr[i] = incl - v;
    if (tid == 1023) g_bsum[blockIdx.x] = incl;
}

__global__ void scan_bsum_kernel() {   // 1 block, 64 threads
    __shared__ int s[64];
    int tid = threadIdx.x;
    int v = (tid < SCANB) ? g_bsum[tid] : 0;
    s[tid] = v;
    __syncthreads();
    #pragma unroll
    for (int off = 1; off < 64; off <<= 1) {
        int t = (tid >= off) ? s[tid - off] : 0;
        __syncthreads();
        s[tid] += t;
        __syncthreads();
    }
    g_boff[tid] = s[tid] - v;
    if (tid == SCANB - 1) g_rowptr[NNODES] = s[tid];
}

__global__ void scan_add_kernel() {
    int i = blockIdx.x * 1024 + threadIdx.x;
    if (i < NNODES) {
        int val = g_rowptr[i] + g_boff[blockIdx.x];
        g_rowptr[i] = val;
        g_cursor[i] = val;
    }
}

__global__ void scatter_kernel(const int* __restrict__ rows,
                               const int* __restrict__ cols,
                               const float* __restrict__ vals) {
    int e = blockIdx.x * blockDim.x + threadIdx.x;
    if (e < NEDGES) {
        int r = rows[e];
        int p = atomicAdd(&g_cursor[r], 1);
        g_col_sorted[p] = cols[e];
        g_val_sorted[p] = vals[e];
    }
}

// ---------------- prep: ego -> bf16 copy (gather source) ----------------
__global__ void ego2bf_kernel(const float* __restrict__ item,
                              const float* __restrict__ user) {
    const int total = NNODES * (D0 / 8);
    int idx = blockIdx.x * blockDim.x + threadIdx.x;
    if (idx >= total) return;
    int n = idx / (D0 / 8);
    int q = (idx - n * (D0 / 8)) * 8;
    const float* src = ((n < N_ITEMS) ? item + (size_t)n * D0
                                      : user + (size_t)(n - N_ITEMS) * D0) + q;
    float4 a = __ldg((const float4*)src);
    float4 b = __ldg((const float4*)(src + 4));
    uint4 o;
    o.x = pack_bf16(__float2bfloat16(a.x), __float2bfloat16(a.y));
    o.y = pack_bf16(__float2bfloat16(a.z), __float2bfloat16(a.w));
    o.z = pack_bf16(__float2bfloat16(b.x), __float2bfloat16(b.y));
    o.w = pack_bf16(__float2bfloat16(b.z), __float2bfloat16(b.w));
    *(uint4*)(g_egobf + (size_t)n * D0 + q) = o;
}

// ---------------- W split+transpose prep ----------------
__global__ void wsplit_kernel(const float* __restrict__ W1,
                              const float* __restrict__ W2) {
    int idx = blockIdx.x * blockDim.x + threadIdx.x;
    if (idx >= D1 * D0) return;
    int n = idx / D0, k = idx - n * D0;
    float w1 = W1[(size_t)k * D1 + n];
    float w2 = W2[(size_t)k * D1 + n];
    __nv_bfloat16 hi, lo;
    split_bf16(w1, hi, lo);
    g_w1hiT[idx] = hi; g_w1loT[idx] = lo;
    split_bf16(w2, hi, lo);
    g_w2hiT[idx] = hi; g_w2loT[idx] = lo;
}

// ---------------- SpMM layer0: bf16 gather, 256-col chunks, unroll 8 --------
// side0[:, kt:kt+256] = A @ egobf[:, kt:kt+256]; 3 passes (blockIdx.y).
__global__ __launch_bounds__(256) void spmm0_chunk_kernel() {
    const int w = threadIdx.x >> 5;      // warp -> row
    const int lane = threadIdx.x & 31;   // lane -> 8 bf16 cols
    const int r = blockIdx.x * 8 + w;
    const int off = blockIdx.y * 256 + lane * 8;
    if (r >= NNODES) return;
    const int e0 = g_rowptr[r], e1 = g_rowptr[r + 1];
    float acc[8];
    #pragma unroll
    for (int q = 0; q < 8; ++q) acc[q] = 0.f;
    int e = e0;
    const int n8 = e0 + ((e1 - e0) & ~7);
    for (; e < n8; e += 8) {
        const __nv_bfloat16* p[8];
        float v[8];
        #pragma unroll
        for (int q = 0; q < 8; ++q) {
            int c = g_col_sorted[e + q];
            v[q] = g_val_sorted[e + q];
            p[q] = g_egobf + (size_t)c * D0 + off;
        }
        uint4 x[8];
        #pragma unroll
        for (int q = 0; q < 8; ++q) x[q] = __ldg((const uint4*)p[q]);
        #pragma unroll
        for (int q = 0; q < 8; ++q) {
            float2 p0 = __bfloat1622float2(*(__nv_bfloat162*)&x[q].x);
            float2 p1 = __bfloat1622float2(*(__nv_bfloat162*)&x[q].y);
            float2 p2 = __bfloat1622float2(*(__nv_bfloat162*)&x[q].z);
            float2 p3 = __bfloat1622float2(*(__nv_bfloat162*)&x[q].w);
            acc[0] += v[q] * p0.x; acc[1] += v[q] * p0.y;
            acc[2] += v[q] * p1.x; acc[3] += v[q] * p1.y;
            acc[4] += v[q] * p2.x; acc[5] += v[q] * p2.y;
            acc[6] += v[q] * p3.x; acc[7] += v[q] * p3.y;
        }
    }
    for (; e < e1; ++e) {
        int   c = g_col_sorted[e];
        float v = g_val_sorted[e];
        uint4 x = __ldg((const uint4*)(g_egobf + (size_t)c * D0 + off));
        float2 p0 = __bfloat1622float2(*(__nv_bfloat162*)&x.x);
        float2 p1 = __bfloat1622float2(*(__nv_bfloat162*)&x.y);
        float2 p2 = __bfloat1622float2(*(__nv_bfloat162*)&x.z);
        float2 p3 = __bfloat1622float2(*(__nv_bfloat162*)&x.w);
        acc[0] += v * p0.x; acc[1] += v * p0.y;
        acc[2] += v * p1.x; acc[3] += v * p1.y;
        acc[4] += v * p2.x; acc[5] += v * p2.y;
        acc[6] += v * p3.x; acc[7] += v * p3.y;
    }
    float* dst = g_side0 + (size_t)r * D0 + off;
    *(float4*)dst       = make_float4(acc[0], acc[1], acc[2], acc[3]);
    *(float4*)(dst + 4) = make_float4(acc[4], acc[5], acc[6], acc[7]);
}

// ---------------- fused GEMM layer0 (mma.sync bf16, 3-term split) ----------------
// ego1 = leaky((side0+ego0)@W1 + b1 + (side0*ego0)@W2 + b2)
// Streams ego0 -> out[:, 0:768]; fuses row-normalize -> out[:, 768:896].
// BM=64, BN=128, BK=16, 128 threads (4 warps 2x2, warp tile 32x64).
#define APAD 24   // row stride in bf16 (48 B, conflict-free ldmatrix)

__global__ __launch_bounds__(128) void gemm0_mma_kernel(
    const float* __restrict__ item, const float* __restrict__ user,
    const float* __restrict__ b1, const float* __restrict__ b2,
    float* __restrict__ out) {
    __shared__ __align__(16) __nv_bfloat16 sAhi[64 * APAD];
    __shared__ __align__(16) __nv_bfloat16 sAlo[64 * APAD];
    __shared__ __align__(16) __nv_bfloat16 sHhi[64 * APAD];
    __shared__ __align__(16) __nv_bfloat16 sHlo[64 * APAD];
    __shared__ __align__(16) __nv_bfloat16 sW1h[128 * APAD];
    __shared__ __align__(16) __nv_bfloat16 sW1l[128 * APAD];
    __shared__ __align__(16) __nv_bfloat16 sW2h[128 * APAD];
    __shared__ __align__(16) __nv_bfloat16 sW2l[128 * APAD];
    __shared__ float bsum[D1];
    __shared__ float rowss[64];

    const int t    = threadIdx.x;
    const int lane = t & 31;
    const int wid  = t >> 5;
    const int wm   = wid >> 1;
    const int wn   = wid & 1;
    const int rm   = blockIdx.x * 64;

    bsum[t] = b1[t] + b2[t];
    if (t < 64) rowss[t] = 0.f;

    const int arow = t >> 1;
    const int akq  = (t & 1) * 8;
    const int gm   = rm + arow;
    const bool mOk = gm < NNODES;
    const float* sideRow = g_side0 + (size_t)gm * D0 + akq;
    const float* egoRow  = ((gm < N_ITEMS) ? item + (size_t)gm * D0
                                           : user + (size_t)(gm - N_ITEMS) * D0) + akq;
    float* outRow = out + (size_t)gm * OUTW + akq;

    const uint32_t aOff = (uint32_t)(((wm * 32 + (lane & 15)) * APAD + (lane >> 4) * 8) * 2);
    const uint32_t addrAhi = smem_u32(sAhi) + aOff;
    const uint32_t addrAlo = smem_u32(sAlo) + aOff;
    const uint32_t addrHhi = smem_u32(sHhi) + aOff;
    const uint32_t addrHlo = smem_u32(sHlo) + aOff;
    const uint32_t bOff4 = (uint32_t)(((wn * 64 + (lane & 7) + ((lane >> 4) << 3)) * APAD
                                       + ((lane >> 3) & 1) * 8) * 2);
    const uint32_t addrW1h = smem_u32(sW1h) + bOff4;
    const uint32_t addrW1l = smem_u32(sW1l) + bOff4;
    const uint32_t addrW2h = smem_u32(sW2h) + bOff4;
    const uint32_t addrW2l = smem_u32(sW2l) + bOff4;
    const uint32_t MT  = 16 * APAD * 2;
    const uint32_t J2T = 16 * APAD * 2;

    float acc[2][8][4];
    #pragma unroll
    for (int i = 0; i < 2; ++i)
        #pragma unroll
        for (int j = 0; j < 8; ++j)
            #pragma unroll
            for (int q = 0; q < 4; ++q) acc[i][j][q] = 0.f;

    for (int kt = 0; kt < D0; kt += 16) {
        {
            float4 sa, sb, ea, eb;
            if (mOk) {
                sa = __ldg((const float4*)(sideRow + kt));
                sb = __ldg((const float4*)(sideRow + kt + 4));
                ea = __ldg((const float4*)(egoRow + kt));
                eb = __ldg((const float4*)(egoRow + kt + 4));
                *(float4*)(outRow + kt) = ea;
                *(float4*)(outRow + kt + 4) = eb;
            } else {
                sa = make_float4(0.f, 0.f, 0.f, 0.f);
                sb = sa; ea = sa; eb = sa;
            }
            float av[8] = {sa.x + ea.x, sa.y + ea.y, sa.z + ea.z, sa.w + ea.w,
                           sb.x + eb.x, sb.y + eb.y, sb.z + eb.z, sb.w + eb.w};
            float hv[8] = {sa.x * ea.x, sa.y * ea.y, sa.z * ea.z, sa.w * ea.w,
                           sb.x * eb.x, sb.y * eb.y, sb.z * eb.z, sb.w * eb.w};
            uint4 uahi, ualo, uhhi, uhlo;
            uint32_t* pa = (uint32_t*)&uahi; uint32_t* pl = (uint32_t*)&ualo;
            uint32_t* ph = (uint32_t*)&uhhi; uint32_t* pm = (uint32_t*)&uhlo;
            __nv_bfloat16 h0, l0, h1, l1;
            #pragma unroll
            for (int q = 0; q < 4; ++q) {
                split_bf16(av[2 * q], h0, l0);
                split_bf16(av[2 * q + 1], h1, l1);
                pa[q] = pack_bf16(h0, h1);
                pl[q] = pack_bf16(l0, l1);
                split_bf16(hv[2 * q], h0, l0);
                split_bf16(hv[2 * q + 1], h1, l1);
                ph[q] = pack_bf16(h0, h1);
                pm[q] = pack_bf16(l0, l1);
            }
            int d = arow * APAD + akq;
            *(uint4*)(sAhi + d) = uahi;
            *(uint4*)(sAlo + d) = ualo;
            *(uint4*)(sHhi + d) = uhhi;
            *(uint4*)(sHlo + d) = uhlo;
        }
        #pragma unroll
        for (int s = 0; s < 2; ++s) {
            int g = s * 128 + t;
            int n = g >> 1;
            int kq = (g & 1) * 8;
            size_t src = (size_t)n * D0 + kt + kq;
            int d = n * APAD + kq;
            *(uint4*)(sW1h + d) = __ldg((const uint4*)(g_w1hiT + src));
            *(uint4*)(sW1l + d) = __ldg((const uint4*)(g_w1loT + src));
            *(uint4*)(sW2h + d) = __ldg((const uint4*)(g_w2hiT + src));
            *(uint4*)(sW2l + d) = __ldg((const uint4*)(g_w2loT + src));
        }
        __syncthreads();

        uint32_t fAhi[2][4], fAlo[2][4], fHhi[2][4], fHlo[2][4];
        ldsm_x4(fAhi[0], addrAhi);       ldsm_x4(fAhi[1], addrAhi + MT);
        ldsm_x4(fAlo[0], addrAlo);       ldsm_x4(fAlo[1], addrAlo + MT);
        ldsm_x4(fHhi[0], addrHhi);       ldsm_x4(fHhi[1], addrHhi + MT);
        ldsm_x4(fHlo[0], addrHlo);       ldsm_x4(fHlo[1], addrHlo + MT);

        #pragma unroll
        for (int jj = 0; jj < 4; ++jj) {
            const int j0 = 2 * jj, j1 = 2 * jj + 1;
            uint32_t b1h[4], b1l[4], b2h[4], b2l[4];
            ldsm_x4(b1h, addrW1h + jj * J2T);
            ldsm_x4(b1l, addrW1l + jj * J2T);
            ldsm_x4(b2h, addrW2h + jj * J2T);
            ldsm_x4(b2l, addrW2l + jj * J2T);
            mma_bf16(acc[0][j0], fAhi[0], b1h);
            mma_bf16(acc[1][j0], fAhi[1], b1h);
            mma_bf16(acc[0][j1], fAhi[0], b1h + 2);
            mma_bf16(acc[1][j1], fAhi[1], b1h + 2);
            mma_bf16(acc[0][j0], fAlo[0], b1h);
            mma_bf16(acc[1][j0], fAlo[1], b1h);
            mma_bf16(acc[0][j1], fAlo[0], b1h + 2);
            mma_bf16(acc[1][j1], fAlo[1], b1h + 2);
            mma_bf16(acc[0][j0], fAhi[0], b1l);
            mma_bf16(acc[1][j0], fAhi[1], b1l);
            mma_bf16(acc[0][j1], fAhi[0], b1l + 2);
            mma_bf16(acc[1][j1], fAhi[1], b1l + 2);
            mma_bf16(acc[0][j0], fHhi[0], b2h);
            mma_bf16(acc[1][j0], fHhi[1], b2h);
            mma_bf16(acc[0][j1], fHhi[0], b2h + 2);
            mma_bf16(acc[1][j1], fHhi[1], b2h + 2);
            mma_bf16(acc[0][j0], fHlo[0], b2h);
            mma_bf16(acc[1][j0], fHlo[1], b2h);
            mma_bf16(acc[0][j1], fHlo[0], b2h + 2);
            mma_bf16(acc[1][j1], fHlo[1], b2h + 2);
            mma_bf16(acc[0][j0], fHhi[0], b2l);
            mma_bf16(acc[1][j0], fHhi[1], b2l);
            mma_bf16(acc[0][j1], fHhi[0], b2l + 2);
            mma_bf16(acc[1][j1], fHhi[1], b2l + 2);
        }
        __syncthreads();
    }

    float vals[2][8][4];
    #pragma unroll
    for (int mt = 0; mt < 2; ++mt) {
        float s0 = 0.f, s1 = 0.f;
        #pragma unroll
        for (int j = 0; j < 8; ++j) {
            int col = wn * 64 + j * 8 + (lane & 3) * 2;
            float bc0 = bsum[col], bc1 = bsum[col + 1];
            float v0 = leaky(acc[mt][j][0] + bc0);
            float v1 = leaky(acc[mt][j][1] + bc1);
            float v2 = leaky(acc[mt][j][2] + bc0);
            float v3 = leaky(acc[mt][j][3] + bc1);
            vals[mt][j][0] = v0; vals[mt][j][1] = v1;
            vals[mt][j][2] = v2; vals[mt][j][3] = v3;
            s0 += v0 * v0 + v1 * v1;
            s1 += v2 * v2 + v3 * v3;
        }
        int lr0 = wm * 32 + mt * 16 + (lane >> 2);
        atomicAdd(&rowss[lr0], s0);
        atomicAdd(&rowss[lr0 + 8], s1);
    }
    __syncthreads();

    #pragma unroll
    for (int mt = 0; mt < 2; ++mt) {
        int lr0 = wm * 32 + mt * 16 + (lane >> 2);
        int row0 = rm + lr0;
        int row1 = row0 + 8;
        float inv0 = 1.f / fmaxf(sqrtf(rowss[lr0]), 1e-12f);
        float inv1 = 1.f / fmaxf(sqrtf(rowss[lr0 + 8]), 1e-12f);
        #pragma unroll
        for (int j = 0; j < 8; ++j) {
            int col = wn * 64 + j * 8 + (lane & 3) * 2;
            if (row0 < NNODES) {
                float2 o = make_float2(vals[mt][j][0], vals[mt][j][1]);
                *(float2*)(g_ego1 + (size_t)row0 * D1 + col) = o;
                float2 n = make_float2(o.x * inv0, o.y * inv0);
                *(float2*)(out + (size_t)row0 * OUTW + D0 + col) = n;
            }
            if (row1 < NNODES) {
                float2 o = make_float2(vals[mt][j][2], vals[mt][j][3]);
                *(float2*)(g_ego1 + (size_t)row1 * D1 + col) = o;
                float2 n = make_float2(o.x * inv1, o.y * inv1);
                *(float2*)(out + (size_t)row1 * OUTW + D0 + col) = n;
            }
        }
    }
}

// ---------------- SpMM layer1: side1 = A @ ego1 (unroll 4) ----------------
__global__ void spmm1_kernel() {
    int w = threadIdx.x >> 5;
    int lane = threadIdx.x & 31;
    int r = blockIdx.x * 4 + w;
    if (r >= NNODES) return;
    int e0 = g_rowptr[r], e1 = g_rowptr[r + 1];
    float4 acc = make_float4(0.f, 0.f, 0.f, 0.f);
    int e = e0;
    int n4 = e0 + ((e1 - e0) & ~3);
    for (; e < n4; e += 4) {
        int c0 = g_col_sorted[e + 0], c1 = g_col_sorted[e + 1];
        int c2 = g_col_sorted[e + 2], c3 = g_col_sorted[e + 3];
        float v0 = g_val_sorted[e + 0], v1 = g_val_sorted[e + 1];
        float v2 = g_val_sorted[e + 2], v3 = g_val_sorted[e + 3];
        float4 x0 = __ldg((const float4*)g_ego1 + (size_t)c0 * (D1 / 4) + lane);
        float4 x1 = __ldg((const float4*)g_ego1 + (size_t)c1 * (D1 / 4) + lane);
        float4 x2 = __ldg((const float4*)g_ego1 + (size_t)c2 * (D1 / 4) + lane);
        float4 x3 = __ldg((const float4*)g_ego1 + (size_t)c3 * (D1 / 4) + lane);
        acc.x += v0 * x0.x + v1 * x1.x + v2 * x2.x + v3 * x3.x;
        acc.y += v0 * x0.y + v1 * x1.y + v2 * x2.y + v3 * x3.y;
        acc.z += v0 * x0.z + v1 * x1.z + v2 * x2.z + v3 * x3.z;
        acc.w += v0 * x0.w + v1 * x1.w + v2 * x2.w + v3 * x3.w;
    }
    for (; e < e1; ++e) {
        int   c = g_col_sorted[e];
        float v = g_val_sorted[e];
        float4 x = __ldg((const float4*)g_ego1 + (size_t)c * (D1 / 4) + lane);
        acc.x += v * x.x; acc.y += v * x.y; acc.z += v * x.z; acc.w += v * x.w;
    }
    ((float4*)g_side1)[(size_t)r * (D1 / 4) + lane] = acc;
}

// ---------------- fused GEMM layer1 + normalize -> out[:, 896:960] ----------------
__global__ __launch_bounds__(256) void gemm1_kernel(
    const float* __restrict__ W1, const float* __restrict__ b1,
    const float* __restrict__ W2, const float* __restrict__ b2,
    float* __restrict__ out) {
    __shared__ __align__(16) float As[16][68];
    __shared__ __align__(16) float Hs[16][68];
    __shared__ __align__(16) float W1s[16][64];
    __shared__ __align__(16) float W2s[16][64];

    int t  = threadIdx.x;
    int tx = t & 31, ty = t >> 5;
    int rm = blockIdx.x * 64;

    float acc[8][2];
    #pragma unroll
    for (int i = 0; i < 8; ++i) { acc[i][0] = 0.f; acc[i][1] = 0.f; }

    int ml = t >> 2;
    int kl = (t & 3) * 4;
    int gm = rm + ml;
    bool mOk = gm < NNODES;
    int wk = t >> 4;
    int wj = (t & 15) * 4;

    for (int kt = 0; kt < D1; kt += 16) {
        if (mOk) {
            float4 s4 = *(const float4*)(g_side1 + (size_t)gm * D1 + kt + kl);
            float4 e4 = *(const float4*)(g_ego1  + (size_t)gm * D1 + kt + kl);
            As[kl + 0][ml] = s4.x + e4.x;  Hs[kl + 0][ml] = s4.x * e4.x;
            As[kl + 1][ml] = s4.y + e4.y;  Hs[kl + 1][ml] = s4.y * e4.y;
            As[kl + 2][ml] = s4.z + e4.z;  Hs[kl + 2][ml] = s4.z * e4.z;
            As[kl + 3][ml] = s4.w + e4.w;  Hs[kl + 3][ml] = s4.w * e4.w;
        } else {
            As[kl + 0][ml] = 0.f; Hs[kl + 0][ml] = 0.f;
            As[kl + 1][ml] = 0.f; Hs[kl + 1][ml] = 0.f;
            As[kl + 2][ml] = 0.f; Hs[kl + 2][ml] = 0.f;
            As[kl + 3][ml] = 0.f; Hs[kl + 3][ml] = 0.f;
        }
        *(float4*)&W1s[wk][wj] = *(const float4*)(W1 + (size_t)(kt + wk) * D2 + wj);
        *(float4*)&W2s[wk][wj] = *(const float4*)(W2 + (size_t)(kt + wk) * D2 + wj);
        __syncthreads();

        #pragma unroll
        for (int k = 0; k < 16; ++k) {
            float2 w1 = *(const float2*)&W1s[k][tx * 2];
            float2 w2 = *(const float2*)&W2s[k][tx * 2];
            float4 a0 = *(const float4*)&As[k][ty * 8];
            float4 a1 = *(const float4*)&As[k][ty * 8 + 4];
            float4 h0 = *(const float4*)&Hs[k][ty * 8];
            float4 h1 = *(const float4*)&Hs[k][ty * 8 + 4];
            float a[8] = {a0.x, a0.y, a0.z, a0.w, a1.x, a1.y, a1.z, a1.w};
            float h[8] = {h0.x, h0.y, h0.z, h0.w, h1.x, h1.y, h1.z, h1.w};
            #pragma unroll
            for (int i = 0; i < 8; ++i) {
                acc[i][0] += a[i] * w1.x + h[i] * w2.x;
                acc[i][1] += a[i] * w1.y + h[i] * w2.y;
            }
        }
        __syncthreads();
    }

    int jc = tx * 2;
    float bs0 = b1[jc] + b2[jc];
    float bs1 = b1[jc + 1] + b2[jc + 1];
    #pragma unroll
    for (int i = 0; i < 8; ++i) {
        int row = rm + ty * 8 + i;
        float v0 = leaky(acc[i][0] + bs0);
        float v1 = leaky(acc[i][1] + bs1);
        float ss = v0 * v0 + v1 * v1;
        #pragma unroll
        for (int off = 16; off > 0; off >>= 1)
            ss += __shfl_xor_sync(0xffffffffu, ss, off);
        float inv = 1.f / fmaxf(sqrtf(ss), 1e-12f);
        if (row < NNODES) {
            float2 o = make_float2(v0 * inv, v1 * inv);
            *(float2*)(out + (size_t)row * OUTW + (D0 + D1) + jc) = o;
        }
    }
}

// ---------------- launch ----------------
extern "C" void kernel_launch(void* const* d_in, const int* in_sizes, int n_in,
                              void* d_out, int out_size) {
    const float* item  = (const float*)d_in[0];
    const float* user  = (const float*)d_in[1];
    const float* W1_0  = (const float*)d_in[2];
    const float* b1_0  = (const float*)d_in[3];
    const float* W2_0  = (const float*)d_in[4];
    const float* b2_0  = (const float*)d_in[5];
    const float* W1_1  = (const float*)d_in[6];
    const float* b1_1  = (const float*)d_in[7];
    const float* W2_1  = (const float*)d_in[8];
    const float* b2_1  = (const float*)d_in[9];
    const float* evals = (const float*)d_in[10];
    const int*   erows = (const int*)d_in[11];
    const int*   ecols = (const int*)d_in[12];
    float* out = (float*)d_out;

    init_hist_kernel<<<64, 256>>>();
    hist_kernel<<<(NEDGES + 255) / 256, 256>>>(erows);
    scan_local_kernel<<<SCANB, 1024>>>();
    scan_bsum_kernel<<<1, 64>>>();
    scan_add_kernel<<<SCANB, 1024>>>();
    scatter_kernel<<<(NEDGES + 255) / 256, 256>>>(erows, ecols, evals);
    ego2bf_kernel<<<(NNODES * (D0 / 8) + 255) / 256, 256>>>(item, user);
    wsplit_kernel<<<(D1 * D0 + 255) / 256, 256>>>(W1_0, W2_0);

    {
        dim3 grid((NNODES + 7) / 8, D0 / 256);   // 3 feature chunks (slow dim)
        spmm0_chunk_kernel<<<grid, 256>>>();
    }
    gemm0_mma_kernel<<<(NNODES + 63) / 64, 128>>>(item, user, b1_0, b2_0, out);
    spmm1_kernel<<<(NNODES + 3) / 4, 128>>>();
    gemm1_kernel<<<(NNODES + 63) / 64, 256>>>(W1_1, b1_1, W2_1, b2_1, out);
}

// round 15
// speedup vs baseline: 1.0819x; 1.0363x over previous
#include <cuda_runtime.h>
#include <cuda_bf16.h>
#include <cstdint>

#define N_ITEMS 30000
#define N_USERS 20000
#define NNODES  50000
#define NEDGES  512000
#define D0 768
#define D1 128
#define D2 64
#define OUTW 960   // 768 + 128 + 64
#define SCANB ((NNODES + 1023) / 1024)   // 49

// ---------------- device scratch (static, no runtime alloc) ----------------
__device__ __nv_bfloat16 g_side0bf[(size_t)NNODES * D0];  // 76.8 MB
__device__ __nv_bfloat16 g_egobf[(size_t)NNODES * D0];    // 76.8 MB (gather source)
__device__ float g_ego1 [(size_t)NNODES * D1];   // 25.6 MB (fp32, for gemm1)
__device__ __nv_bfloat16 g_ego1bf[(size_t)NNODES * D1];   // 12.8 MB (spmm1 gather)
__device__ float g_side1[(size_t)NNODES * D1];   // 25.6 MB
__device__ int   g_hist[NNODES];
__device__ int   g_rowptr[NNODES + 1];
__device__ int   g_cursor[NNODES];
__device__ int   g_col_sorted[NEDGES];
__device__ float g_val_sorted[NEDGES];
__device__ int   g_bsum[64];
__device__ int   g_boff[64];
// split + transposed weights for tensor-core gemm0: [N=128][K=768] bf16
__device__ __nv_bfloat16 g_w1hiT[D1 * D0];
__device__ __nv_bfloat16 g_w1loT[D1 * D0];
__device__ __nv_bfloat16 g_w2hiT[D1 * D0];
__device__ __nv_bfloat16 g_w2loT[D1 * D0];

__device__ __forceinline__ float leaky(float v) { return v > 0.f ? v : 0.01f * v; }

__device__ __forceinline__ uint32_t smem_u32(const void* p) {
    uint32_t a;
    asm("{ .reg .u64 t; cvta.to.shared.u64 t, %1; cvt.u32.u64 %0, t; }"
        : "=r"(a) : "l"(p));
    return a;
}
__device__ __forceinline__ void ldsm_x4(uint32_t* r, uint32_t addr) {
    asm volatile("ldmatrix.sync.aligned.m8n8.x4.shared.b16 {%0,%1,%2,%3}, [%4];"
                 : "=r"(r[0]), "=r"(r[1]), "=r"(r[2]), "=r"(r[3]) : "r"(addr));
}
__device__ __forceinline__ void mma_bf16(float* d, const uint32_t* a, const uint32_t* b) {
    asm volatile(
        "mma.sync.aligned.m16n8k16.row.col.f32.bf16.bf16.f32 "
        "{%0,%1,%2,%3}, {%4,%5,%6,%7}, {%8,%9}, {%0,%1,%2,%3};"
        : "+f"(d[0]), "+f"(d[1]), "+f"(d[2]), "+f"(d[3])
        : "r"(a[0]), "r"(a[1]), "r"(a[2]), "r"(a[3]), "r"(b[0]), "r"(b[1]));
}
__device__ __forceinline__ uint32_t pack_bf16(__nv_bfloat16 a, __nv_bfloat16 b) {
    return ((uint32_t)__bfloat16_as_ushort(b) << 16) | (uint32_t)__bfloat16_as_ushort(a);
}
__device__ __forceinline__ void split_bf16(float x, __nv_bfloat16& hi, __nv_bfloat16& lo) {
    hi = __float2bfloat16(x);
    lo = __float2bfloat16(x - __bfloat162float(hi));
}

// ---------------- CSR build ----------------
__global__ void init_hist_kernel() {
    for (int i = blockIdx.x * blockDim.x + threadIdx.x; i < NNODES;
         i += gridDim.x * blockDim.x)
        g_hist[i] = 0;
}

__global__ void hist_kernel(const int* __restrict__ rows) {
    int e = blockIdx.x * blockDim.x + threadIdx.x;
    if (e < NEDGES) atomicAdd(&g_hist[rows[e]], 1);
}

__global__ void scan_local_kernel() {
    __shared__ int wsum[32];
    int tid = threadIdx.x, lane = tid & 31, wid = tid >> 5;
    int i = blockIdx.x * 1024 + tid;
    int v = (i < NNODES) ? g_hist[i] : 0;
    int x = v;
    #pragma unroll
    for (int off = 1; off < 32; off <<= 1) {
        int t = __shfl_up_sync(0xffffffffu, x, off);
        if (lane >= off) x += t;
    }
    if (lane == 31) wsum[wid] = x;
    __syncthreads();
    if (wid == 0) {
        int w = wsum[lane];
        #pragma unroll
        for (int off = 1; off < 32; off <<= 1) {
            int t = __shfl_up_sync(0xffffffffu, w, off);
            if (lane >= off) w += t;
        }
        wsum[lane] = w;
    }
    __syncthreads();
    int warp_off = (wid == 0) ? 0 : wsum[wid - 1];
    int incl = x + warp_off;
    if (i < NNODES) g_rowptr[i] = incl - v;
    if (tid == 1023) g_bsum[blockIdx.x] = incl;
}

__global__ void scan_bsum_kernel() {   // 1 block, 64 threads
    __shared__ int s[64];
    int tid = threadIdx.x;
    int v = (tid < SCANB) ? g_bsum[tid] : 0;
    s[tid] = v;
    __syncthreads();
    #pragma unroll
    for (int off = 1; off < 64; off <<= 1) {
        int t = (tid >= off) ? s[tid - off] : 0;
        __syncthreads();
        s[tid] += t;
        __syncthreads();
    }
    g_boff[tid] = s[tid] - v;
    if (tid == SCANB - 1) g_rowptr[NNODES] = s[tid];
}

__global__ void scan_add_kernel() {
    int i = blockIdx.x * 1024 + threadIdx.x;
    if (i < NNODES) {
        int val = g_rowptr[i] + g_boff[blockIdx.x];
        g_rowptr[i] = val;
        g_cursor[i] = val;
    }
}

__global__ void scatter_kernel(const int* __restrict__ rows,
                               const int* __restrict__ cols,
                               const float* __restrict__ vals) {
    int e = blockIdx.x * blockDim.x + threadIdx.x;
    if (e < NEDGES) {
        int r = rows[e];
        int p = atomicAdd(&g_cursor[r], 1);
        g_col_sorted[p] = cols[e];
        g_val_sorted[p] = vals[e];
    }
}

// ---------------- prep: ego -> bf16 copy (gather source) ----------------
__global__ void ego2bf_kernel(const float* __restrict__ item,
                              const float* __restrict__ user) {
    const int total = NNODES * (D0 / 8);
    int idx = blockIdx.x * blockDim.x + threadIdx.x;
    if (idx >= total) return;
    int n = idx / (D0 / 8);
    int q = (idx - n * (D0 / 8)) * 8;
    const float* src = ((n < N_ITEMS) ? item + (size_t)n * D0
                                      : user + (size_t)(n - N_ITEMS) * D0) + q;
    float4 a = __ldg((const float4*)src);
    float4 b = __ldg((const float4*)(src + 4));
    uint4 o;
    o.x = pack_bf16(__float2bfloat16(a.x), __float2bfloat16(a.y));
    o.y = pack_bf16(__float2bfloat16(a.z), __float2bfloat16(a.w));
    o.z = pack_bf16(__float2bfloat16(b.x), __float2bfloat16(b.y));
    o.w = pack_bf16(__float2bfloat16(b.z), __float2bfloat16(b.w));
    *(uint4*)(g_egobf + (size_t)n * D0 + q) = o;
}

// ---------------- W split+transpose prep ----------------
__global__ void wsplit_kernel(const float* __restrict__ W1,
                              const float* __restrict__ W2) {
    int idx = blockIdx.x * blockDim.x + threadIdx.x;
    if (idx >= D1 * D0) return;
    int n = idx / D0, k = idx - n * D0;
    float w1 = W1[(size_t)k * D1 + n];
    float w2 = W2[(size_t)k * D1 + n];
    __nv_bfloat16 hi, lo;
    split_bf16(w1, hi, lo);
    g_w1hiT[idx] = hi; g_w1loT[idx] = lo;
    split_bf16(w2, hi, lo);
    g_w2hiT[idx] = hi; g_w2loT[idx] = lo;
}

// ---------------- SpMM layer0: bf16 gather, 256-col chunks, unroll 8 --------
// side0bf[:, kt:kt+256] = A @ egobf[:, kt:kt+256]; 3 passes (blockIdx.y).
__global__ __launch_bounds__(256) void spmm0_chunk_kernel() {
    const int w = threadIdx.x >> 5;      // warp -> row
    const int lane = threadIdx.x & 31;   // lane -> 8 bf16 cols
    const int r = blockIdx.x * 8 + w;
    const int off = blockIdx.y * 256 + lane * 8;
    if (r >= NNODES) return;
    const int e0 = g_rowptr[r], e1 = g_rowptr[r + 1];
    float acc[8];
    #pragma unroll
    for (int q = 0; q < 8; ++q) acc[q] = 0.f;
    int e = e0;
    const int n8 = e0 + ((e1 - e0) & ~7);
    for (; e < n8; e += 8) {
        const __nv_bfloat16* p[8];
        float v[8];
        #pragma unroll
        for (int q = 0; q < 8; ++q) {
            int c = g_col_sorted[e + q];
            v[q] = g_val_sorted[e + q];
            p[q] = g_egobf + (size_t)c * D0 + off;
        }
        uint4 x[8];
        #pragma unroll
        for (int q = 0; q < 8; ++q) x[q] = __ldg((const uint4*)p[q]);
        #pragma unroll
        for (int q = 0; q < 8; ++q) {
            float2 p0 = __bfloat1622float2(*(__nv_bfloat162*)&x[q].x);
            float2 p1 = __bfloat1622float2(*(__nv_bfloat162*)&x[q].y);
            float2 p2 = __bfloat1622float2(*(__nv_bfloat162*)&x[q].z);
            float2 p3 = __bfloat1622float2(*(__nv_bfloat162*)&x[q].w);
            acc[0] += v[q] * p0.x; acc[1] += v[q] * p0.y;
            acc[2] += v[q] * p1.x; acc[3] += v[q] * p1.y;
            acc[4] += v[q] * p2.x; acc[5] += v[q] * p2.y;
            acc[6] += v[q] * p3.x; acc[7] += v[q] * p3.y;
        }
    }
    for (; e < e1; ++e) {
        int   c = g_col_sorted[e];
        float v = g_val_sorted[e];
        uint4 x = __ldg((const uint4*)(g_egobf + (size_t)c * D0 + off));
        float2 p0 = __bfloat1622float2(*(__nv_bfloat162*)&x.x);
        float2 p1 = __bfloat1622float2(*(__nv_bfloat162*)&x.y);
        float2 p2 = __bfloat1622float2(*(__nv_bfloat162*)&x.z);
        float2 p3 = __bfloat1622float2(*(__nv_bfloat162*)&x.w);
        acc[0] += v * p0.x; acc[1] += v * p0.y;
        acc[2] += v * p1.x; acc[3] += v * p1.y;
        acc[4] += v * p2.x; acc[5] += v * p2.y;
        acc[6] += v * p3.x; acc[7] += v * p3.y;
    }
    // store side0 as bf16 (8 values = one uint4)
    uint4 o;
    o.x = pack_bf16(__float2bfloat16(acc[0]), __float2bfloat16(acc[1]));
    o.y = pack_bf16(__float2bfloat16(acc[2]), __float2bfloat16(acc[3]));
    o.z = pack_bf16(__float2bfloat16(acc[4]), __float2bfloat16(acc[5]));
    o.w = pack_bf16(__float2bfloat16(acc[6]), __float2bfloat16(acc[7]));
    *(uint4*)(g_side0bf + (size_t)r * D0 + off) = o;
}

// ---------------- fused GEMM layer0 (mma.sync bf16, 3-term split) ----------------
// ego1 = leaky((side0+ego0)@W1 + b1 + (side0*ego0)@W2 + b2)
// Streams ego0 -> out[:, 0:768]; fuses row-normalize -> out[:, 768:896].
// BM=64, BN=128, BK=16, 128 threads (4 warps 2x2, warp tile 32x64).
#define APAD 24   // row stride in bf16 (48 B, conflict-free ldmatrix)

__global__ __launch_bounds__(128) void gemm0_mma_kernel(
    const float* __restrict__ item, const float* __restrict__ user,
    const float* __restrict__ b1, const float* __restrict__ b2,
    float* __restrict__ out) {
    __shared__ __align__(16) __nv_bfloat16 sAhi[64 * APAD];
    __shared__ __align__(16) __nv_bfloat16 sAlo[64 * APAD];
    __shared__ __align__(16) __nv_bfloat16 sHhi[64 * APAD];
    __shared__ __align__(16) __nv_bfloat16 sHlo[64 * APAD];
    __shared__ __align__(16) __nv_bfloat16 sW1h[128 * APAD];
    __shared__ __align__(16) __nv_bfloat16 sW1l[128 * APAD];
    __shared__ __align__(16) __nv_bfloat16 sW2h[128 * APAD];
    __shared__ __align__(16) __nv_bfloat16 sW2l[128 * APAD];
    __shared__ float bsum[D1];
    __shared__ float rowss[64];

    const int t    = threadIdx.x;
    const int lane = t & 31;
    const int wid  = t >> 5;
    const int wm   = wid >> 1;
    const int wn   = wid & 1;
    const int rm   = blockIdx.x * 64;

    bsum[t] = b1[t] + b2[t];
    if (t < 64) rowss[t] = 0.f;

    const int arow = t >> 1;
    const int akq  = (t & 1) * 8;
    const int gm   = rm + arow;
    const bool mOk = gm < NNODES;
    const __nv_bfloat16* sideRow = g_side0bf + (size_t)gm * D0 + akq;
    const float* egoRow  = ((gm < N_ITEMS) ? item + (size_t)gm * D0
                                           : user + (size_t)(gm - N_ITEMS) * D0) + akq;
    float* outRow = out + (size_t)gm * OUTW + akq;

    const uint32_t aOff = (uint32_t)(((wm * 32 + (lane & 15)) * APAD + (lane >> 4) * 8) * 2);
    const uint32_t addrAhi = smem_u32(sAhi) + aOff;
    const uint32_t addrAlo = smem_u32(sAlo) + aOff;
    const uint32_t addrHhi = smem_u32(sHhi) + aOff;
    const uint32_t addrHlo = smem_u32(sHlo) + aOff;
    const uint32_t bOff4 = (uint32_t)(((wn * 64 + (lane & 7) + ((lane >> 4) << 3)) * APAD
                                       + ((lane >> 3) & 1) * 8) * 2);
    const uint32_t addrW1h = smem_u32(sW1h) + bOff4;
    const uint32_t addrW1l = smem_u32(sW1l) + bOff4;
    const uint32_t addrW2h = smem_u32(sW2h) + bOff4;
    const uint32_t addrW2l = smem_u32(sW2l) + bOff4;
    const uint32_t MT  = 16 * APAD * 2;
    const uint32_t J2T = 16 * APAD * 2;

    float acc[2][8][4];
    #pragma unroll
    for (int i = 0; i < 2; ++i)
        #pragma unroll
        for (int j = 0; j < 8; ++j)
            #pragma unroll
            for (int q = 0; q < 4; ++q) acc[i][j][q] = 0.f;

    for (int kt = 0; kt < D0; kt += 16) {
        {
            float sv[8];
            float4 ea, eb;
            if (mOk) {
                uint4 sx = __ldg((const uint4*)(sideRow + kt));
                float2 q0 = __bfloat1622float2(*(__nv_bfloat162*)&sx.x);
                float2 q1 = __bfloat1622float2(*(__nv_bfloat162*)&sx.y);
                float2 q2 = __bfloat1622float2(*(__nv_bfloat162*)&sx.z);
                float2 q3 = __bfloat1622float2(*(__nv_bfloat162*)&sx.w);
                sv[0] = q0.x; sv[1] = q0.y; sv[2] = q1.x; sv[3] = q1.y;
                sv[4] = q2.x; sv[5] = q2.y; sv[6] = q3.x; sv[7] = q3.y;
                ea = __ldg((const float4*)(egoRow + kt));
                eb = __ldg((const float4*)(egoRow + kt + 4));
                *(float4*)(outRow + kt) = ea;
                *(float4*)(outRow + kt + 4) = eb;
            } else {
                #pragma unroll
                for (int q = 0; q < 8; ++q) sv[q] = 0.f;
                ea = make_float4(0.f, 0.f, 0.f, 0.f);
                eb = ea;
            }
            float ev[8] = {ea.x, ea.y, ea.z, ea.w, eb.x, eb.y, eb.z, eb.w};
            float av[8], hv[8];
            #pragma unroll
            for (int q = 0; q < 8; ++q) {
                av[q] = sv[q] + ev[q];
                hv[q] = sv[q] * ev[q];
            }
            uint4 uahi, ualo, uhhi, uhlo;
            uint32_t* pa = (uint32_t*)&uahi; uint32_t* pl = (uint32_t*)&ualo;
            uint32_t* ph = (uint32_t*)&uhhi; uint32_t* pm = (uint32_t*)&uhlo;
            __nv_bfloat16 h0, l0, h1, l1;
            #pragma unroll
            for (int q = 0; q < 4; ++q) {
                split_bf16(av[2 * q], h0, l0);
                split_bf16(av[2 * q + 1], h1, l1);
                pa[q] = pack_bf16(h0, h1);
                pl[q] = pack_bf16(l0, l1);
                split_bf16(hv[2 * q], h0, l0);
                split_bf16(hv[2 * q + 1], h1, l1);
                ph[q] = pack_bf16(h0, h1);
                pm[q] = pack_bf16(l0, l1);
            }
            int d = arow * APAD + akq;
            *(uint4*)(sAhi + d) = uahi;
            *(uint4*)(sAlo + d) = ualo;
            *(uint4*)(sHhi + d) = uhhi;
            *(uint4*)(sHlo + d) = uhlo;
        }
        #pragma unroll
        for (int s = 0; s < 2; ++s) {
            int g = s * 128 + t;
            int n = g >> 1;
            int kq = (g & 1) * 8;
            size_t src = (size_t)n * D0 + kt + kq;
            int d = n * APAD + kq;
            *(uint4*)(sW1h + d) = __ldg((const uint4*)(g_w1hiT + src));
            *(uint4*)(sW1l + d) = __ldg((const uint4*)(g_w1loT + src));
            *(uint4*)(sW2h + d) = __ldg((const uint4*)(g_w2hiT + src));
            *(uint4*)(sW2l + d) = __ldg((const uint4*)(g_w2loT + src));
        }
        __syncthreads();

        uint32_t fAhi[2][4], fAlo[2][4], fHhi[2][4], fHlo[2][4];
        ldsm_x4(fAhi[0], addrAhi);       ldsm_x4(fAhi[1], addrAhi + MT);
        ldsm_x4(fAlo[0], addrAlo);       ldsm_x4(fAlo[1], addrAlo + MT);
        ldsm_x4(fHhi[0], addrHhi);       ldsm_x4(fHhi[1], addrHhi + MT);
        ldsm_x4(fHlo[0], addrHlo);       ldsm_x4(fHlo[1], addrHlo + MT);

        #pragma unroll
        for (int jj = 0; jj < 4; ++jj) {
            const int j0 = 2 * jj, j1 = 2 * jj + 1;
            uint32_t b1h[4], b1l[4], b2h[4], b2l[4];
            ldsm_x4(b1h, addrW1h + jj * J2T);
            ldsm_x4(b1l, addrW1l + jj * J2T);
            ldsm_x4(b2h, addrW2h + jj * J2T);
            ldsm_x4(b2l, addrW2l + jj * J2T);
            mma_bf16(acc[0][j0], fAhi[0], b1h);
            mma_bf16(acc[1][j0], fAhi[1], b1h);
            mma_bf16(acc[0][j1], fAhi[0], b1h + 2);
            mma_bf16(acc[1][j1], fAhi[1], b1h + 2);
            mma_bf16(acc[0][j0], fAlo[0], b1h);
            mma_bf16(acc[1][j0], fAlo[1], b1h);
            mma_bf16(acc[0][j1], fAlo[0], b1h + 2);
            mma_bf16(acc[1][j1], fAlo[1], b1h + 2);
            mma_bf16(acc[0][j0], fAhi[0], b1l);
            mma_bf16(acc[1][j0], fAhi[1], b1l);
            mma_bf16(acc[0][j1], fAhi[0], b1l + 2);
            mma_bf16(acc[1][j1], fAhi[1], b1l + 2);
            mma_bf16(acc[0][j0], fHhi[0], b2h);
            mma_bf16(acc[1][j0], fHhi[1], b2h);
            mma_bf16(acc[0][j1], fHhi[0], b2h + 2);
            mma_bf16(acc[1][j1], fHhi[1], b2h + 2);
            mma_bf16(acc[0][j0], fHlo[0], b2h);
            mma_bf16(acc[1][j0], fHlo[1], b2h);
            mma_bf16(acc[0][j1], fHlo[0], b2h + 2);
            mma_bf16(acc[1][j1], fHlo[1], b2h + 2);
            mma_bf16(acc[0][j0], fHhi[0], b2l);
            mma_bf16(acc[1][j0], fHhi[1], b2l);
            mma_bf16(acc[0][j1], fHhi[0], b2l + 2);
            mma_bf16(acc[1][j1], fHhi[1], b2l + 2);
        }
        __syncthreads();
    }

    float vals[2][8][4];
    #pragma unroll
    for (int mt = 0; mt < 2; ++mt) {
        float s0 = 0.f, s1 = 0.f;
        #pragma unroll
        for (int j = 0; j < 8; ++j) {
            int col = wn * 64 + j * 8 + (lane & 3) * 2;
            float bc0 = bsum[col], bc1 = bsum[col + 1];
            float v0 = leaky(acc[mt][j][0] + bc0);
            float v1 = leaky(acc[mt][j][1] + bc1);
            float v2 = leaky(acc[mt][j][2] + bc0);
            float v3 = leaky(acc[mt][j][3] + bc1);
            vals[mt][j][0] = v0; vals[mt][j][1] = v1;
            vals[mt][j][2] = v2; vals[mt][j][3] = v3;
            s0 += v0 * v0 + v1 * v1;
            s1 += v2 * v2 + v3 * v3;
        }
        int lr0 = wm * 32 + mt * 16 + (lane >> 2);
        atomicAdd(&rowss[lr0], s0);
        atomicAdd(&rowss[lr0 + 8], s1);
    }
    __syncthreads();

    #pragma unroll
    for (int mt = 0; mt < 2; ++mt) {
        int lr0 = wm * 32 + mt * 16 + (lane >> 2);
        int row0 = rm + lr0;
        int row1 = row0 + 8;
        float inv0 = 1.f / fmaxf(sqrtf(rowss[lr0]), 1e-12f);
        float inv1 = 1.f / fmaxf(sqrtf(rowss[lr0 + 8]), 1e-12f);
        #pragma unroll
        for (int j = 0; j < 8; ++j) {
            int col = wn * 64 + j * 8 + (lane & 3) * 2;
            if (row0 < NNODES) {
                float2 o = make_float2(vals[mt][j][0], vals[mt][j][1]);
                *(float2*)(g_ego1 + (size_t)row0 * D1 + col) = o;
                *(uint32_t*)(g_ego1bf + (size_t)row0 * D1 + col) =
                    pack_bf16(__float2bfloat16(o.x), __float2bfloat16(o.y));
                float2 n = make_float2(o.x * inv0, o.y * inv0);
                *(float2*)(out + (size_t)row0 * OUTW + D0 + col) = n;
            }
            if (row1 < NNODES) {
                float2 o = make_float2(vals[mt][j][2], vals[mt][j][3]);
                *(float2*)(g_ego1 + (size_t)row1 * D1 + col) = o;
                *(uint32_t*)(g_ego1bf + (size_t)row1 * D1 + col) =
                    pack_bf16(__float2bfloat16(o.x), __float2bfloat16(o.y));
                float2 n = make_float2(o.x * inv1, o.y * inv1);
                *(float2*)(out + (size_t)row1 * OUTW + D0 + col) = n;
            }
        }
    }
}

// ---------------- SpMM layer1: side1 = A @ ego1bf (unroll 4) ----------------
__global__ void spmm1_kernel() {
    int w = threadIdx.x >> 5;
    int lane = threadIdx.x & 31;
    int r = blockIdx.x * 4 + w;
    if (r >= NNODES) return;
    int e0 = g_rowptr[r], e1 = g_rowptr[r + 1];
    float4 acc = make_float4(0.f, 0.f, 0.f, 0.f);
    int e = e0;
    int n4 = e0 + ((e1 - e0) & ~3);
    for (; e < n4; e += 4) {
        int c0 = g_col_sorted[e + 0], c1 = g_col_sorted[e + 1];
        int c2 = g_col_sorted[e + 2], c3 = g_col_sorted[e + 3];
        float v0 = g_val_sorted[e + 0], v1 = g_val_sorted[e + 1];
        float v2 = g_val_sorted[e + 2], v3 = g_val_sorted[e + 3];
        uint2 x0 = __ldg((const uint2*)(g_ego1bf + (size_t)c0 * D1 + lane * 4));
        uint2 x1 = __ldg((const uint2*)(g_ego1bf + (size_t)c1 * D1 + lane * 4));
        uint2 x2 = __ldg((const uint2*)(g_ego1bf + (size_t)c2 * D1 + lane * 4));
        uint2 x3 = __ldg((const uint2*)(g_ego1bf + (size_t)c3 * D1 + lane * 4));
        float2 a0 = __bfloat1622float2(*(__nv_bfloat162*)&x0.x);
        float2 b0 = __bfloat1622float2(*(__nv_bfloat162*)&x0.y);
        float2 a1 = __bfloat1622float2(*(__nv_bfloat162*)&x1.x);
        float2 b1 = __bfloat1622float2(*(__nv_bfloat162*)&x1.y);
        float2 a2 = __bfloat1622float2(*(__nv_bfloat162*)&x2.x);
        float2 b2 = __bfloat1622float2(*(__nv_bfloat162*)&x2.y);
        float2 a3 = __bfloat1622float2(*(__nv_bfloat162*)&x3.x);
        float2 b3 = __bfloat1622float2(*(__nv_bfloat162*)&x3.y);
        acc.x += v0 * a0.x + v1 * a1.x + v2 * a2.x + v3 * a3.x;
        acc.y += v0 * a0.y + v1 * a1.y + v2 * a2.y + v3 * a3.y;
        acc.z += v0 * b0.x + v1 * b1.x + v2 * b2.x + v3 * b3.x;
        acc.w += v0 * b0.y + v1 * b1.y + v2 * b2.y + v3 * b3.y;
    }
    for (; e < e1; ++e) {
        int   c = g_col_sorted[e];
        float v = g_val_sorted[e];
        uint2 x = __ldg((const uint2*)(g_ego1bf + (size_t)c * D1 + lane * 4));
        float2 a = __bfloat1622float2(*(__nv_bfloat162*)&x.x);
        float2 b = __bfloat1622float2(*(__nv_bfloat162*)&x.y);
        acc.x += v * a.x; acc.y += v * a.y; acc.z += v * b.x; acc.w += v * b.y;
    }
    *(float4*)(g_side1 + (size_t)r * D1 + lane * 4) = acc;
}

// ---------------- fused GEMM layer1 + normalize -> out[:, 896:960] ----------------
__global__ __launch_bounds__(256) void gemm1_kernel(
    const float* __restrict__ W1, const float* __restrict__ b1,
    const float* __restrict__ W2, const float* __restrict__ b2,
    float* __restrict__ out) {
    __shared__ __align__(16) float As[16][68];
    __shared__ __align__(16) float Hs[16][68];
    __shared__ __align__(16) float W1s[16][64];
    __shared__ __align__(16) float W2s[16][64];

    int t  = threadIdx.x;
    int tx = t & 31, ty = t >> 5;
    int rm = blockIdx.x * 64;

    float acc[8][2];
    #pragma unroll
    for (int i = 0; i < 8; ++i) { acc[i][0] = 0.f; acc[i][1] = 0.f; }

    int ml = t >> 2;
    int kl = (t & 3) * 4;
    int gm = rm + ml;
    bool mOk = gm < NNODES;
    int wk = t >> 4;
    int wj = (t & 15) * 4;

    for (int kt = 0; kt < D1; kt += 16) {
        if (mOk) {
            float4 s4 = *(const float4*)(g_side1 + (size_t)gm * D1 + kt + kl);
            float4 e4 = *(const float4*)(g_ego1  + (size_t)gm * D1 + kt + kl);
            As[kl + 0][ml] = s4.x + e4.x;  Hs[kl + 0][ml] = s4.x * e4.x;
            As[kl + 1][ml] = s4.y + e4.y;  Hs[kl + 1][ml] = s4.y * e4.y;
            As[kl + 2][ml] = s4.z + e4.z;  Hs[kl + 2][ml] = s4.z * e4.z;
            As[kl + 3][ml] = s4.w + e4.w;  Hs[kl + 3][ml] = s4.w * e4.w;
        } else {
            As[kl + 0][ml] = 0.f; Hs[kl + 0][ml] = 0.f;
            As[kl + 1][ml] = 0.f; Hs[kl + 1][ml] = 0.f;
            As[kl + 2][ml] = 0.f; Hs[kl + 2][ml] = 0.f;
            As[kl + 3][ml] = 0.f; Hs[kl + 3][ml] = 0.f;
        }
        *(float4*)&W1s[wk][wj] = *(const float4*)(W1 + (size_t)(kt + wk) * D2 + wj);
        *(float4*)&W2s[wk][wj] = *(const float4*)(W2 + (size_t)(kt + wk) * D2 + wj);
        __syncthreads();

        #pragma unroll
        for (int k = 0; k < 16; ++k) {
            float2 w1 = *(const float2*)&W1s[k][tx * 2];
            float2 w2 = *(const float2*)&W2s[k][tx * 2];
            float4 a0 = *(const float4*)&As[k][ty * 8];
            float4 a1 = *(const float4*)&As[k][ty * 8 + 4];
            float4 h0 = *(const float4*)&Hs[k][ty * 8];
            float4 h1 = *(const float4*)&Hs[k][ty * 8 + 4];
            float a[8] = {a0.x, a0.y, a0.z, a0.w, a1.x, a1.y, a1.z, a1.w};
            float h[8] = {h0.x, h0.y, h0.z, h0.w, h1.x, h1.y, h1.z, h1.w};
            #pragma unroll
            for (int i = 0; i < 8; ++i) {
                acc[i][0] += a[i] * w1.x + h[i] * w2.x;
                acc[i][1] += a[i] * w1.y + h[i] * w2.y;
            }
        }
        __syncthreads();
    }

    int jc = tx * 2;
    float bs0 = b1[jc] + b2[jc];
    float bs1 = b1[jc + 1] + b2[jc + 1];
    #pragma unroll
    for (int i = 0; i < 8; ++i) {
        int row = rm + ty * 8 + i;
        float v0 = leaky(acc[i][0] + bs0);
        float v1 = leaky(acc[i][1] + bs1);
        float ss = v0 * v0 + v1 * v1;
        #pragma unroll
        for (int off = 16; off > 0; off >>= 1)
            ss += __shfl_xor_sync(0xffffffffu, ss, off);
        float inv = 1.f / fmaxf(sqrtf(ss), 1e-12f);
        if (row < NNODES) {
            float2 o = make_float2(v0 * inv, v1 * inv);
            *(float2*)(out + (size_t)row * OUTW + (D0 + D1) + jc) = o;
        }
    }
}

// ---------------- launch ----------------
extern "C" void kernel_launch(void* const* d_in, const int* in_sizes, int n_in,
                              void* d_out, int out_size) {
    const float* item  = (const float*)d_in[0];
    const float* user  = (const float*)d_in[1];
    const float* W1_0  = (const float*)d_in[2];
    const float* b1_0  = (const float*)d_in[3];
    const float* W2_0  = (const float*)d_in[4];
    const float* b2_0  = (const float*)d_in[5];
    const float* W1_1  = (const float*)d_in[6];
    const float* b1_1  = (const float*)d_in[7];
    const float* W2_1  = (const float*)d_in[8];
    const float* b2_1  = (const float*)d_in[9];
    const float* evals = (const float*)d_in[10];
    const int*   erows = (const int*)d_in[11];
    const int*   ecols = (const int*)d_in[12];
    float* out = (float*)d_out;

    init_hist_kernel<<<64, 256>>>();
    hist_kernel<<<(NEDGES + 255) / 256, 256>>>(erows);
    scan_local_kernel<<<SCANB, 1024>>>();
    scan_bsum_kernel<<<1, 64>>>();
    scan_add_kernel<<<SCANB, 1024>>>();
    scatter_kernel<<<(NEDGES + 255) / 256, 256>>>(erows, ecols, evals);
    ego2bf_kernel<<<(NNODES * (D0 / 8) + 255) / 256, 256>>>(item, user);
    wsplit_kernel<<<(D1 * D0 + 255) / 256, 256>>>(W1_0, W2_0);

    {
        dim3 grid((NNODES + 7) / 8, D0 / 256);   // 3 feature chunks (slow dim)
        spmm0_chunk_kernel<<<grid, 256>>>();
    }
    gemm0_mma_kernel<<<(NNODES + 63) / 64, 128>>>(item, user, b1_0, b2_0, out);
    spmm1_kernel<<<(NNODES + 3) / 4, 128>>>();
    gemm1_kernel<<<(NNODES + 63) / 64, 256>>>(W1_1, b1_1, W2_1, b2_1, out);
}

// round 16
// speedup vs baseline: 1.0833x; 1.0013x over previous
#include <cuda_runtime.h>
#include <cuda_bf16.h>
#include <cstdint>

#define N_ITEMS 30000
#define N_USERS 20000
#define NNODES  50000
#define NEDGES  512000
#define D0 768
#define D1 128
#define D2 64
#define OUTW 960   // 768 + 128 + 64
#define SCANB ((NNODES + 1023) / 1024)   // 49

// ---------------- device scratch (static, no runtime alloc) ----------------
__device__ __nv_bfloat16 g_side0bf[(size_t)NNODES * D0];  // 76.8 MB
__device__ __nv_bfloat16 g_egobf[(size_t)NNODES * D0];    // 76.8 MB (gather source)
__device__ float g_ego1 [(size_t)NNODES * D1];   // 25.6 MB (fp32, for gemm1)
__device__ __nv_bfloat16 g_ego1bf[(size_t)NNODES * D1];   // 12.8 MB (spmm1 gather)
__device__ float g_side1[(size_t)NNODES * D1];   // 25.6 MB
__device__ int   g_hist[NNODES];
__device__ int   g_rowptr[NNODES + 1];
__device__ int   g_cursor[NNODES];
__device__ int   g_col_sorted[NEDGES];
__device__ float g_val_sorted[NEDGES];
__device__ int   g_bsum[64];
__device__ int   g_boff[64];
// split + transposed weights for tensor-core gemm0: [N=128][K=768] bf16
__device__ __nv_bfloat16 g_w1hiT[D1 * D0];
__device__ __nv_bfloat16 g_w1loT[D1 * D0];
__device__ __nv_bfloat16 g_w2hiT[D1 * D0];
__device__ __nv_bfloat16 g_w2loT[D1 * D0];

__device__ __forceinline__ float leaky(float v) { return v > 0.f ? v : 0.01f * v; }

__device__ __forceinline__ uint32_t smem_u32(const void* p) {
    uint32_t a;
    asm("{ .reg .u64 t; cvta.to.shared.u64 t, %1; cvt.u32.u64 %0, t; }"
        : "=r"(a) : "l"(p));
    return a;
}
__device__ __forceinline__ void ldsm_x4(uint32_t* r, uint32_t addr) {
    asm volatile("ldmatrix.sync.aligned.m8n8.x4.shared.b16 {%0,%1,%2,%3}, [%4];"
                 : "=r"(r[0]), "=r"(r[1]), "=r"(r[2]), "=r"(r[3]) : "r"(addr));
}
__device__ __forceinline__ void mma_bf16(float* d, const uint32_t* a, const uint32_t* b) {
    asm volatile(
        "mma.sync.aligned.m16n8k16.row.col.f32.bf16.bf16.f32 "
        "{%0,%1,%2,%3}, {%4,%5,%6,%7}, {%8,%9}, {%0,%1,%2,%3};"
        : "+f"(d[0]), "+f"(d[1]), "+f"(d[2]), "+f"(d[3])
        : "r"(a[0]), "r"(a[1]), "r"(a[2]), "r"(a[3]), "r"(b[0]), "r"(b[1]));
}
__device__ __forceinline__ uint32_t pack_bf16(__nv_bfloat16 a, __nv_bfloat16 b) {
    return ((uint32_t)__bfloat16_as_ushort(b) << 16) | (uint32_t)__bfloat16_as_ushort(a);
}
__device__ __forceinline__ void split_bf16(float x, __nv_bfloat16& hi, __nv_bfloat16& lo) {
    hi = __float2bfloat16(x);
    lo = __float2bfloat16(x - __bfloat162float(hi));
}

// ---------------- CSR build ----------------
__global__ void init_hist_kernel() {
    for (int i = blockIdx.x * blockDim.x + threadIdx.x; i < NNODES;
         i += gridDim.x * blockDim.x)
        g_hist[i] = 0;
}

__global__ void hist_kernel(const int* __restrict__ rows) {
    int e = blockIdx.x * blockDim.x + threadIdx.x;
    if (e < NEDGES) atomicAdd(&g_hist[rows[e]], 1);
}

__global__ void scan_local_kernel() {
    __shared__ int wsum[32];
    int tid = threadIdx.x, lane = tid & 31, wid = tid >> 5;
    int i = blockIdx.x * 1024 + tid;
    int v = (i < NNODES) ? g_hist[i] : 0;
    int x = v;
    #pragma unroll
    for (int off = 1; off < 32; off <<= 1) {
        int t = __shfl_up_sync(0xffffffffu, x, off);
        if (lane >= off) x += t;
    }
    if (lane == 31) wsum[wid] = x;
    __syncthreads();
    if (wid == 0) {
        int w = wsum[lane];
        #pragma unroll
        for (int off = 1; off < 32; off <<= 1) {
            int t = __shfl_up_sync(0xffffffffu, w, off);
            if (lane >= off) w += t;
        }
        wsum[lane] = w;
    }
    __syncthreads();
    int warp_off = (wid == 0) ? 0 : wsum[wid - 1];
    int incl = x + warp_off;
    if (i < NNODES) g_rowptr[i] = incl - v;
    if (tid == 1023) g_bsum[blockIdx.x] = incl;
}

__global__ void scan_bsum_kernel() {   // 1 block, 64 threads
    __shared__ int s[64];
    int tid = threadIdx.x;
    int v = (tid < SCANB) ? g_bsum[tid] : 0;
    s[tid] = v;
    __syncthreads();
    #pragma unroll
    for (int off = 1; off < 64; off <<= 1) {
        int t = (tid >= off) ? s[tid - off] : 0;
        __syncthreads();
        s[tid] += t;
        __syncthreads();
    }
    g_boff[tid] = s[tid] - v;
    if (tid == SCANB - 1) g_rowptr[NNODES] = s[tid];
}

__global__ void scan_add_kernel() {
    int i = blockIdx.x * 1024 + threadIdx.x;
    if (i < NNODES) {
        int val = g_rowptr[i] + g_boff[blockIdx.x];
        g_rowptr[i] = val;
        g_cursor[i] = val;
    }
}

__global__ void scatter_kernel(const int* __restrict__ rows,
                               const int* __restrict__ cols,
                               const float* __restrict__ vals) {
    int e = blockIdx.x * blockDim.x + threadIdx.x;
    if (e < NEDGES) {
        int r = rows[e];
        int p = atomicAdd(&g_cursor[r], 1);
        g_col_sorted[p] = cols[e];
        g_val_sorted[p] = vals[e];
    }
}

// ---------------- prep: ego -> bf16 copy (gather source) ----------------
__global__ void ego2bf_kernel(const float* __restrict__ item,
                              const float* __restrict__ user) {
    const int total = NNODES * (D0 / 8);
    int idx = blockIdx.x * blockDim.x + threadIdx.x;
    if (idx >= total) return;
    int n = idx / (D0 / 8);
    int q = (idx - n * (D0 / 8)) * 8;
    const float* src = ((n < N_ITEMS) ? item + (size_t)n * D0
                                      : user + (size_t)(n - N_ITEMS) * D0) + q;
    float4 a = __ldg((const float4*)src);
    float4 b = __ldg((const float4*)(src + 4));
    uint4 o;
    o.x = pack_bf16(__float2bfloat16(a.x), __float2bfloat16(a.y));
    o.y = pack_bf16(__float2bfloat16(a.z), __float2bfloat16(a.w));
    o.z = pack_bf16(__float2bfloat16(b.x), __float2bfloat16(b.y));
    o.w = pack_bf16(__float2bfloat16(b.z), __float2bfloat16(b.w));
    *(uint4*)(g_egobf + (size_t)n * D0 + q) = o;
}

// ---------------- W split+transpose prep ----------------
__global__ void wsplit_kernel(const float* __restrict__ W1,
                              const float* __restrict__ W2) {
    int idx = blockIdx.x * blockDim.x + threadIdx.x;
    if (idx >= D1 * D0) return;
    int n = idx / D0, k = idx - n * D0;
    float w1 = W1[(size_t)k * D1 + n];
    float w2 = W2[(size_t)k * D1 + n];
    __nv_bfloat16 hi, lo;
    split_bf16(w1, hi, lo);
    g_w1hiT[idx] = hi; g_w1loT[idx] = lo;
    split_bf16(w2, hi, lo);
    g_w2hiT[idx] = hi; g_w2loT[idx] = lo;
}

// ---------------- SpMM layer0: bf16 gather, 256-col chunks, unroll 8 --------
// side0bf[:, kt:kt+256] = A @ egobf[:, kt:kt+256]; 3 passes (blockIdx.y).
__global__ __launch_bounds__(256) void spmm0_chunk_kernel() {
    const int w = threadIdx.x >> 5;      // warp -> row
    const int lane = threadIdx.x & 31;   // lane -> 8 bf16 cols
    const int r = blockIdx.x * 8 + w;
    const int off = blockIdx.y * 256 + lane * 8;
    if (r >= NNODES) return;
    const int e0 = g_rowptr[r], e1 = g_rowptr[r + 1];
    float acc[8];
    #pragma unroll
    for (int q = 0; q < 8; ++q) acc[q] = 0.f;
    int e = e0;
    const int n8 = e0 + ((e1 - e0) & ~7);
    for (; e < n8; e += 8) {
        const __nv_bfloat16* p[8];
        float v[8];
        #pragma unroll
        for (int q = 0; q < 8; ++q) {
            int c = g_col_sorted[e + q];
            v[q] = g_val_sorted[e + q];
            p[q] = g_egobf + (size_t)c * D0 + off;
        }
        uint4 x[8];
        #pragma unroll
        for (int q = 0; q < 8; ++q) x[q] = __ldg((const uint4*)p[q]);
        #pragma unroll
        for (int q = 0; q < 8; ++q) {
            float2 p0 = __bfloat1622float2(*(__nv_bfloat162*)&x[q].x);
            float2 p1 = __bfloat1622float2(*(__nv_bfloat162*)&x[q].y);
            float2 p2 = __bfloat1622float2(*(__nv_bfloat162*)&x[q].z);
            float2 p3 = __bfloat1622float2(*(__nv_bfloat162*)&x[q].w);
            acc[0] += v[q] * p0.x; acc[1] += v[q] * p0.y;
            acc[2] += v[q] * p1.x; acc[3] += v[q] * p1.y;
            acc[4] += v[q] * p2.x; acc[5] += v[q] * p2.y;
            acc[6] += v[q] * p3.x; acc[7] += v[q] * p3.y;
        }
    }
    for (; e < e1; ++e) {
        int   c = g_col_sorted[e];
        float v = g_val_sorted[e];
        uint4 x = __ldg((const uint4*)(g_egobf + (size_t)c * D0 + off));
        float2 p0 = __bfloat1622float2(*(__nv_bfloat162*)&x.x);
        float2 p1 = __bfloat1622float2(*(__nv_bfloat162*)&x.y);
        float2 p2 = __bfloat1622float2(*(__nv_bfloat162*)&x.z);
        float2 p3 = __bfloat1622float2(*(__nv_bfloat162*)&x.w);
        acc[0] += v * p0.x; acc[1] += v * p0.y;
        acc[2] += v * p1.x; acc[3] += v * p1.y;
        acc[4] += v * p2.x; acc[5] += v * p2.y;
        acc[6] += v * p3.x; acc[7] += v * p3.y;
    }
    // store side0 as bf16 (8 values = one uint4)
    uint4 o;
    o.x = pack_bf16(__float2bfloat16(acc[0]), __float2bfloat16(acc[1]));
    o.y = pack_bf16(__float2bfloat16(acc[2]), __float2bfloat16(acc[3]));
    o.z = pack_bf16(__float2bfloat16(acc[4]), __float2bfloat16(acc[5]));
    o.w = pack_bf16(__float2bfloat16(acc[6]), __float2bfloat16(acc[7]));
    *(uint4*)(g_side0bf + (size_t)r * D0 + off) = o;
}

// ---------------- fused GEMM layer0 (mma.sync bf16, 3-term split) ----------------
// ego1 = leaky((side0+ego0)@W1 + b1 + (side0*ego0)@W2 + b2)
// Streams ego0 -> out[:, 0:768]; fuses row-normalize -> out[:, 768:896].
// BM=64, BN=128, BK=16, 128 threads (4 warps 2x2, warp tile 32x64).
#define APAD 24   // row stride in bf16 (48 B, conflict-free ldmatrix)

__global__ __launch_bounds__(128) void gemm0_mma_kernel(
    const float* __restrict__ item, const float* __restrict__ user,
    const float* __restrict__ b1, const float* __restrict__ b2,
    float* __restrict__ out) {
    __shared__ __align__(16) __nv_bfloat16 sAhi[64 * APAD];
    __shared__ __align__(16) __nv_bfloat16 sAlo[64 * APAD];
    __shared__ __align__(16) __nv_bfloat16 sHhi[64 * APAD];
    __shared__ __align__(16) __nv_bfloat16 sHlo[64 * APAD];
    __shared__ __align__(16) __nv_bfloat16 sW1h[128 * APAD];
    __shared__ __align__(16) __nv_bfloat16 sW1l[128 * APAD];
    __shared__ __align__(16) __nv_bfloat16 sW2h[128 * APAD];
    __shared__ __align__(16) __nv_bfloat16 sW2l[128 * APAD];
    __shared__ float bsum[D1];
    __shared__ float rowss[64];

    const int t    = threadIdx.x;
    const int lane = t & 31;
    const int wid  = t >> 5;
    const int wm   = wid >> 1;
    const int wn   = wid & 1;
    const int rm   = blockIdx.x * 64;

    bsum[t] = b1[t] + b2[t];
    if (t < 64) rowss[t] = 0.f;

    const int arow = t >> 1;
    const int akq  = (t & 1) * 8;
    const int gm   = rm + arow;
    const bool mOk = gm < NNODES;
    const __nv_bfloat16* sideRow = g_side0bf + (size_t)gm * D0 + akq;
    const float* egoRow  = ((gm < N_ITEMS) ? item + (size_t)gm * D0
                                           : user + (size_t)(gm - N_ITEMS) * D0) + akq;
    float* outRow = out + (size_t)gm * OUTW + akq;

    const uint32_t aOff = (uint32_t)(((wm * 32 + (lane & 15)) * APAD + (lane >> 4) * 8) * 2);
    const uint32_t addrAhi = smem_u32(sAhi) + aOff;
    const uint32_t addrAlo = smem_u32(sAlo) + aOff;
    const uint32_t addrHhi = smem_u32(sHhi) + aOff;
    const uint32_t addrHlo = smem_u32(sHlo) + aOff;
    const uint32_t bOff4 = (uint32_t)(((wn * 64 + (lane & 7) + ((lane >> 4) << 3)) * APAD
                                       + ((lane >> 3) & 1) * 8) * 2);
    const uint32_t addrW1h = smem_u32(sW1h) + bOff4;
    const uint32_t addrW1l = smem_u32(sW1l) + bOff4;
    const uint32_t addrW2h = smem_u32(sW2h) + bOff4;
    const uint32_t addrW2l = smem_u32(sW2l) + bOff4;
    const uint32_t MT  = 16 * APAD * 2;
    const uint32_t J2T = 16 * APAD * 2;

    float acc[2][8][4];
    #pragma unroll
    for (int i = 0; i < 2; ++i)
        #pragma unroll
        for (int j = 0; j < 8; ++j)
            #pragma unroll
            for (int q = 0; q < 4; ++q) acc[i][j][q] = 0.f;

    for (int kt = 0; kt < D0; kt += 16) {
        {
            float sv[8];
            float4 ea, eb;
            if (mOk) {
                uint4 sx = __ldg((const uint4*)(sideRow + kt));
                float2 q0 = __bfloat1622float2(*(__nv_bfloat162*)&sx.x);
                float2 q1 = __bfloat1622float2(*(__nv_bfloat162*)&sx.y);
                float2 q2 = __bfloat1622float2(*(__nv_bfloat162*)&sx.z);
                float2 q3 = __bfloat1622float2(*(__nv_bfloat162*)&sx.w);
                sv[0] = q0.x; sv[1] = q0.y; sv[2] = q1.x; sv[3] = q1.y;
                sv[4] = q2.x; sv[5] = q2.y; sv[6] = q3.x; sv[7] = q3.y;
                ea = __ldg((const float4*)(egoRow + kt));
                eb = __ldg((const float4*)(egoRow + kt + 4));
                *(float4*)(outRow + kt) = ea;
                *(float4*)(outRow + kt + 4) = eb;
            } else {
                #pragma unroll
                for (int q = 0; q < 8; ++q) sv[q] = 0.f;
                ea = make_float4(0.f, 0.f, 0.f, 0.f);
                eb = ea;
            }
            float ev[8] = {ea.x, ea.y, ea.z, ea.w, eb.x, eb.y, eb.z, eb.w};
            float av[8], hv[8];
            #pragma unroll
            for (int q = 0; q < 8; ++q) {
                av[q] = sv[q] + ev[q];
                hv[q] = sv[q] * ev[q];
            }
            uint4 uahi, ualo, uhhi, uhlo;
            uint32_t* pa = (uint32_t*)&uahi; uint32_t* pl = (uint32_t*)&ualo;
            uint32_t* ph = (uint32_t*)&uhhi; uint32_t* pm = (uint32_t*)&uhlo;
            __nv_bfloat16 h0, l0, h1, l1;
            #pragma unroll
            for (int q = 0; q < 4; ++q) {
                split_bf16(av[2 * q], h0, l0);
                split_bf16(av[2 * q + 1], h1, l1);
                pa[q] = pack_bf16(h0, h1);
                pl[q] = pack_bf16(l0, l1);
                split_bf16(hv[2 * q], h0, l0);
                split_bf16(hv[2 * q + 1], h1, l1);
                ph[q] = pack_bf16(h0, h1);
                pm[q] = pack_bf16(l0, l1);
            }
            int d = arow * APAD + akq;
            *(uint4*)(sAhi + d) = uahi;
            *(uint4*)(sAlo + d) = ualo;
            *(uint4*)(sHhi + d) = uhhi;
            *(uint4*)(sHlo + d) = uhlo;
        }
        #pragma unroll
        for (int s = 0; s < 2; ++s) {
            int g = s * 128 + t;
            int n = g >> 1;
            int kq = (g & 1) * 8;
            size_t src = (size_t)n * D0 + kt + kq;
            int d = n * APAD + kq;
            *(uint4*)(sW1h + d) = __ldg((const uint4*)(g_w1hiT + src));
            *(uint4*)(sW1l + d) = __ldg((const uint4*)(g_w1loT + src));
            *(uint4*)(sW2h + d) = __ldg((const uint4*)(g_w2hiT + src));
            *(uint4*)(sW2l + d) = __ldg((const uint4*)(g_w2loT + src));
        }
        __syncthreads();

        uint32_t fAhi[2][4], fAlo[2][4], fHhi[2][4], fHlo[2][4];
        ldsm_x4(fAhi[0], addrAhi);       ldsm_x4(fAhi[1], addrAhi + MT);
        ldsm_x4(fAlo[0], addrAlo);       ldsm_x4(fAlo[1], addrAlo + MT);
        ldsm_x4(fHhi[0], addrHhi);       ldsm_x4(fHhi[1], addrHhi + MT);
        ldsm_x4(fHlo[0], addrHlo);       ldsm_x4(fHlo[1], addrHlo + MT);

        #pragma unroll
        for (int jj = 0; jj < 4; ++jj) {
            const int j0 = 2 * jj, j1 = 2 * jj + 1;
            uint32_t b1h[4], b1l[4], b2h[4], b2l[4];
            ldsm_x4(b1h, addrW1h + jj * J2T);
            ldsm_x4(b1l, addrW1l + jj * J2T);
            ldsm_x4(b2h, addrW2h + jj * J2T);
            ldsm_x4(b2l, addrW2l + jj * J2T);
            mma_bf16(acc[0][j0], fAhi[0], b1h);
            mma_bf16(acc[1][j0], fAhi[1], b1h);
            mma_bf16(acc[0][j1], fAhi[0], b1h + 2);
            mma_bf16(acc[1][j1], fAhi[1], b1h + 2);
            mma_bf16(acc[0][j0], fAlo[0], b1h);
            mma_bf16(acc[1][j0], fAlo[1], b1h);
            mma_bf16(acc[0][j1], fAlo[0], b1h + 2);
            mma_bf16(acc[1][j1], fAlo[1], b1h + 2);
            mma_bf16(acc[0][j0], fAhi[0], b1l);
            mma_bf16(acc[1][j0], fAhi[1], b1l);
            mma_bf16(acc[0][j1], fAhi[0], b1l + 2);
            mma_bf16(acc[1][j1], fAhi[1], b1l + 2);
            mma_bf16(acc[0][j0], fHhi[0], b2h);
            mma_bf16(acc[1][j0], fHhi[1], b2h);
            mma_bf16(acc[0][j1], fHhi[0], b2h + 2);
            mma_bf16(acc[1][j1], fHhi[1], b2h + 2);
            mma_bf16(acc[0][j0], fHlo[0], b2h);
            mma_bf16(acc[1][j0], fHlo[1], b2h);
            mma_bf16(acc[0][j1], fHlo[0], b2h + 2);
            mma_bf16(acc[1][j1], fHlo[1], b2h + 2);
            mma_bf16(acc[0][j0], fHhi[0], b2l);
            mma_bf16(acc[1][j0], fHhi[1], b2l);
            mma_bf16(acc[0][j1], fHhi[0], b2l + 2);
            mma_bf16(acc[1][j1], fHhi[1], b2l + 2);
        }
        __syncthreads();
    }

    float vals[2][8][4];
    #pragma unroll
    for (int mt = 0; mt < 2; ++mt) {
        float s0 = 0.f, s1 = 0.f;
        #pragma unroll
        for (int j = 0; j < 8; ++j) {
            int col = wn * 64 + j * 8 + (lane & 3) * 2;
            float bc0 = bsum[col], bc1 = bsum[col + 1];
            float v0 = leaky(acc[mt][j][0] + bc0);
            float v1 = leaky(acc[mt][j][1] + bc1);
            float v2 = leaky(acc[mt][j][2] + bc0);
            float v3 = leaky(acc[mt][j][3] + bc1);
            vals[mt][j][0] = v0; vals[mt][j][1] = v1;
            vals[mt][j][2] = v2; vals[mt][j][3] = v3;
            s0 += v0 * v0 + v1 * v1;
            s1 += v2 * v2 + v3 * v3;
        }
        int lr0 = wm * 32 + mt * 16 + (lane >> 2);
        atomicAdd(&rowss[lr0], s0);
        atomicAdd(&rowss[lr0 + 8], s1);
    }
    __syncthreads();

    #pragma unroll
    for (int mt = 0; mt < 2; ++mt) {
        int lr0 = wm * 32 + mt * 16 + (lane >> 2);
        int row0 = rm + lr0;
        int row1 = row0 + 8;
        float inv0 = 1.f / fmaxf(sqrtf(rowss[lr0]), 1e-12f);
        float inv1 = 1.f / fmaxf(sqrtf(rowss[lr0 + 8]), 1e-12f);
        #pragma unroll
        for (int j = 0; j < 8; ++j) {
            int col = wn * 64 + j * 8 + (lane & 3) * 2;
            if (row0 < NNODES) {
                float2 o = make_float2(vals[mt][j][0], vals[mt][j][1]);
                *(float2*)(g_ego1 + (size_t)row0 * D1 + col) = o;
                *(uint32_t*)(g_ego1bf + (size_t)row0 * D1 + col) =
                    pack_bf16(__float2bfloat16(o.x), __float2bfloat16(o.y));
                float2 n = make_float2(o.x * inv0, o.y * inv0);
                *(float2*)(out + (size_t)row0 * OUTW + D0 + col) = n;
            }
            if (row1 < NNODES) {
                float2 o = make_float2(vals[mt][j][2], vals[mt][j][3]);
                *(float2*)(g_ego1 + (size_t)row1 * D1 + col) = o;
                *(uint32_t*)(g_ego1bf + (size_t)row1 * D1 + col) =
                    pack_bf16(__float2bfloat16(o.x), __float2bfloat16(o.y));
                float2 n = make_float2(o.x * inv1, o.y * inv1);
                *(float2*)(out + (size_t)row1 * OUTW + D0 + col) = n;
            }
        }
    }
}

// ---------------- SpMM layer1: side1 = A @ ego1bf (unroll 4) ----------------
__global__ void spmm1_kernel() {
    int w = threadIdx.x >> 5;
    int lane = threadIdx.x & 31;
    int r = blockIdx.x * 4 + w;
    if (r >= NNODES) return;
    int e0 = g_rowptr[r], e1 = g_rowptr[r + 1];
    float4 acc = make_float4(0.f, 0.f, 0.f, 0.f);
    int e = e0;
    int n4 = e0 + ((e1 - e0) & ~3);
    for (; e < n4; e += 4) {
        int c0 = g_col_sorted[e + 0], c1 = g_col_sorted[e + 1];
        int c2 = g_col_sorted[e + 2], c3 = g_col_sorted[e + 3];
        float v0 = g_val_sorted[e + 0], v1 = g_val_sorted[e + 1];
        float v2 = g_val_sorted[e + 2], v3 = g_val_sorted[e + 3];
        uint2 x0 = __ldg((const uint2*)(g_ego1bf + (size_t)c0 * D1 + lane * 4));
        uint2 x1 = __ldg((const uint2*)(g_ego1bf + (size_t)c1 * D1 + lane * 4));
        uint2 x2 = __ldg((const uint2*)(g_ego1bf + (size_t)c2 * D1 + lane * 4));
        uint2 x3 = __ldg((const uint2*)(g_ego1bf + (size_t)c3 * D1 + lane * 4));
        float2 a0 = __bfloat1622float2(*(__nv_bfloat162*)&x0.x);
        float2 b0 = __bfloat1622float2(*(__nv_bfloat162*)&x0.y);
        float2 a1 = __bfloat1622float2(*(__nv_bfloat162*)&x1.x);
        float2 b1 = __bfloat1622float2(*(__nv_bfloat162*)&x1.y);
        float2 a2 = __bfloat1622float2(*(__nv_bfloat162*)&x2.x);
        float2 b2 = __bfloat1622float2(*(__nv_bfloat162*)&x2.y);
        float2 a3 = __bfloat1622float2(*(__nv_bfloat162*)&x3.x);
        float2 b3 = __bfloat1622float2(*(__nv_bfloat162*)&x3.y);
        acc.x += v0 * a0.x + v1 * a1.x + v2 * a2.x + v3 * a3.x;
        acc.y += v0 * a0.y + v1 * a1.y + v2 * a2.y + v3 * a3.y;
        acc.z += v0 * b0.x + v1 * b1.x + v2 * b2.x + v3 * b3.x;
        acc.w += v0 * b0.y + v1 * b1.y + v2 * b2.y + v3 * b3.y;
    }
    for (; e < e1; ++e) {
        int   c = g_col_sorted[e];
        float v = g_val_sorted[e];
        uint2 x = __ldg((const uint2*)(g_ego1bf + (size_t)c * D1 + lane * 4));
        float2 a = __bfloat1622float2(*(__nv_bfloat162*)&x.x);
        float2 b = __bfloat1622float2(*(__nv_bfloat162*)&x.y);
        acc.x += v * a.x; acc.y += v * a.y; acc.z += v * b.x; acc.w += v * b.y;
    }
    *(float4*)(g_side1 + (size_t)r * D1 + lane * 4) = acc;
}

// ---------------- fused GEMM layer1 + normalize -> out[:, 896:960] ----------------
__global__ __launch_bounds__(256) void gemm1_kernel(
    const float* __restrict__ W1, const float* __restrict__ b1,
    const float* __restrict__ W2, const float* __restrict__ b2,
    float* __restrict__ out) {
    __shared__ __align__(16) float As[16][68];
    __shared__ __align__(16) float Hs[16][68];
    __shared__ __align__(16) float W1s[16][64];
    __shared__ __align__(16) float W2s[16][64];

    int t  = threadIdx.x;
    int tx = t & 31, ty = t >> 5;
    int rm = blockIdx.x * 64;

    float acc[8][2];
    #pragma unroll
    for (int i = 0; i < 8; ++i) { acc[i][0] = 0.f; acc[i][1] = 0.f; }

    int ml = t >> 2;
    int kl = (t & 3) * 4;
    int gm = rm + ml;
    bool mOk = gm < NNODES;
    int wk = t >> 4;
    int wj = (t & 15) * 4;

    for (int kt = 0; kt < D1; kt += 16) {
        if (mOk) {
            float4 s4 = *(const float4*)(g_side1 + (size_t)gm * D1 + kt + kl);
            float4 e4 = *(const float4*)(g_ego1  + (size_t)gm * D1 + kt + kl);
            As[kl + 0][ml] = s4.x + e4.x;  Hs[kl + 0][ml] = s4.x * e4.x;
            As[kl + 1][ml] = s4.y + e4.y;  Hs[kl + 1][ml] = s4.y * e4.y;
            As[kl + 2][ml] = s4.z + e4.z;  Hs[kl + 2][ml] = s4.z * e4.z;
            As[kl + 3][ml] = s4.w + e4.w;  Hs[kl + 3][ml] = s4.w * e4.w;
        } else {
            As[kl + 0][ml] = 0.f; Hs[kl + 0][ml] = 0.f;
            As[kl + 1][ml] = 0.f; Hs[kl + 1][ml] = 0.f;
            As[kl + 2][ml] = 0.f; Hs[kl + 2][ml] = 0.f;
            As[kl + 3][ml] = 0.f; Hs[kl + 3][ml] = 0.f;
        }
        *(float4*)&W1s[wk][wj] = *(const float4*)(W1 + (size_t)(kt + wk) * D2 + wj);
        *(float4*)&W2s[wk][wj] = *(const float4*)(W2 + (size_t)(kt + wk) * D2 + wj);
        __syncthreads();

        #pragma unroll
        for (int k = 0; k < 16; ++k) {
            float2 w1 = *(const float2*)&W1s[k][tx * 2];
            float2 w2 = *(const float2*)&W2s[k][tx * 2];
            float4 a0 = *(const float4*)&As[k][ty * 8];
            float4 a1 = *(const float4*)&As[k][ty * 8 + 4];
            float4 h0 = *(const float4*)&Hs[k][ty * 8];
            float4 h1 = *(const float4*)&Hs[k][ty * 8 + 4];
            float a[8] = {a0.x, a0.y, a0.z, a0.w, a1.x, a1.y, a1.z, a1.w};
            float h[8] = {h0.x, h0.y, h0.z, h0.w, h1.x, h1.y, h1.z, h1.w};
            #pragma unroll
            for (int i = 0; i < 8; ++i) {
                acc[i][0] += a[i] * w1.x + h[i] * w2.x;
                acc[i][1] += a[i] * w1.y + h[i] * w2.y;
            }
        }
        __syncthreads();
    }

    int jc = tx * 2;
    float bs0 = b1[jc] + b2[jc];
    float bs1 = b1[jc + 1] + b2[jc + 1];
    #pragma unroll
    for (int i = 0; i < 8; ++i) {
        int row = rm + ty * 8 + i;
        float v0 = leaky(acc[i][0] + bs0);
        float v1 = leaky(acc[i][1] + bs1);
        float ss = v0 * v0 + v1 * v1;
        #pragma unroll
        for (int off = 16; off > 0; off >>= 1)
            ss += __shfl_xor_sync(0xffffffffu, ss, off);
        float inv = 1.f / fmaxf(sqrtf(ss), 1e-12f);
        if (row < NNODES) {
            float2 o = make_float2(v0 * inv, v1 * inv);
            *(float2*)(out + (size_t)row * OUTW + (D0 + D1) + jc) = o;
        }
    }
}

// ---------------- launch ----------------
extern "C" void kernel_launch(void* const* d_in, const int* in_sizes, int n_in,
                              void* d_out, int out_size) {
    const float* item  = (const float*)d_in[0];
    const float* user  = (const float*)d_in[1];
    const float* W1_0  = (const float*)d_in[2];
    const float* b1_0  = (const float*)d_in[3];
    const float* W2_0  = (const float*)d_in[4];
    const float* b2_0  = (const float*)d_in[5];
    const float* W1_1  = (const float*)d_in[6];
    const float* b1_1  = (const float*)d_in[7];
    const float* W2_1  = (const float*)d_in[8];
    const float* b2_1  = (const float*)d_in[9];
    const float* evals = (const float*)d_in[10];
    const int*   erows = (const int*)d_in[11];
    const int*   ecols = (const int*)d_in[12];
    float* out = (float*)d_out;

    init_hist_kernel<<<64, 256>>>();
    hist_kernel<<<(NEDGES + 255) / 256, 256>>>(erows);
    scan_local_kernel<<<SCANB, 1024>>>();
    scan_bsum_kernel<<<1, 64>>>();
    scan_add_kernel<<<SCANB, 1024>>>();
    scatter_kernel<<<(NEDGES + 255) / 256, 256>>>(erows, ecols, evals);
    ego2bf_kernel<<<(NNODES * (D0 / 8) + 255) / 256, 256>>>(item, user);
    wsplit_kernel<<<(D1 * D0 + 255) / 256, 256>>>(W1_0, W2_0);

    {
        dim3 grid((NNODES + 7) / 8, D0 / 256);   // 3 feature chunks (slow dim)
        spmm0_chunk_kernel<<<grid, 256>>>();
    }
    gemm0_mma_kernel<<<(NNODES + 63) / 64, 128>>>(item, user, b1_0, b2_0, out);
    spmm1_kernel<<<(NNODES + 3) / 4, 128>>>();
    gemm1_kernel<<<(NNODES + 63) / 64, 256>>>(W1_1, b1_1, W2_1, b2_1, out);
}

// round 17
// speedup vs baseline: 1.0962x; 1.0119x over previous
#include <cuda_runtime.h>
#include <cuda_bf16.h>
#include <cstdint>

#define N_ITEMS 30000
#define N_USERS 20000
#define NNODES  50000
#define NEDGES  512000
#define D0 768
#define D1 128
#define D2 64
#define OUTW 960   // 768 + 128 + 64
#define SCANB ((NNODES + 1023) / 1024)   // 49

// ---------------- device scratch (static, no runtime alloc) ----------------
__device__ __nv_bfloat16 g_side0bf[(size_t)NNODES * D0];  // 76.8 MB
__device__ __nv_bfloat16 g_egobf[(size_t)NNODES * D0];    // 76.8 MB (gather source)
__device__ float g_ego1 [(size_t)NNODES * D1];   // 25.6 MB (fp32, for gemm1)
__device__ __nv_bfloat16 g_ego1bf[(size_t)NNODES * D1];   // 12.8 MB (spmm1 gather)
__device__ float g_side1[(size_t)NNODES * D1];   // 25.6 MB
__device__ int   g_hist[NNODES];
__device__ int   g_rowptr[NNODES + 1];
__device__ int   g_cursor[NNODES];
__device__ int   g_col_sorted[NEDGES];
__device__ float g_val_sorted[NEDGES];
__device__ int   g_bsum[64];
// split + transposed weights for tensor-core gemm0: [N=128][K=768] bf16
__device__ __nv_bfloat16 g_w1hiT[D1 * D0];
__device__ __nv_bfloat16 g_w1loT[D1 * D0];
__device__ __nv_bfloat16 g_w2hiT[D1 * D0];
__device__ __nv_bfloat16 g_w2loT[D1 * D0];

__device__ __forceinline__ float leaky(float v) { return v > 0.f ? v : 0.01f * v; }

__device__ __forceinline__ uint32_t smem_u32(const void* p) {
    uint32_t a;
    asm("{ .reg .u64 t; cvta.to.shared.u64 t, %1; cvt.u32.u64 %0, t; }"
        : "=r"(a) : "l"(p));
    return a;
}
__device__ __forceinline__ void ldsm_x4(uint32_t* r, uint32_t addr) {
    asm volatile("ldmatrix.sync.aligned.m8n8.x4.shared.b16 {%0,%1,%2,%3}, [%4];"
                 : "=r"(r[0]), "=r"(r[1]), "=r"(r[2]), "=r"(r[3]) : "r"(addr));
}
__device__ __forceinline__ void mma_bf16(float* d, const uint32_t* a, const uint32_t* b) {
    asm volatile(
        "mma.sync.aligned.m16n8k16.row.col.f32.bf16.bf16.f32 "
        "{%0,%1,%2,%3}, {%4,%5,%6,%7}, {%8,%9}, {%0,%1,%2,%3};"
        : "+f"(d[0]), "+f"(d[1]), "+f"(d[2]), "+f"(d[3])
        : "r"(a[0]), "r"(a[1]), "r"(a[2]), "r"(a[3]), "r"(b[0]), "r"(b[1]));
}
__device__ __forceinline__ uint32_t pack_bf16(__nv_bfloat16 a, __nv_bfloat16 b) {
    return ((uint32_t)__bfloat16_as_ushort(b) << 16) | (uint32_t)__bfloat16_as_ushort(a);
}
__device__ __forceinline__ void split_bf16(float x, __nv_bfloat16& hi, __nv_bfloat16& lo) {
    hi = __float2bfloat16(x);
    lo = __float2bfloat16(x - __bfloat162float(hi));
}

// ---------------- prep: init hist + ego->bf16 + W split (one launch) --------
#define PREP_TOTAL (NNODES * (D0 / 8))   // 4.8M, dominates
__global__ void prep_kernel(const float* __restrict__ item,
                            const float* __restrict__ user,
                            const float* __restrict__ W1,
                            const float* __restrict__ W2) {
    int idx = blockIdx.x * blockDim.x + threadIdx.x;
    if (idx < NNODES) g_hist[idx] = 0;
    if (idx < D1 * D0) {
        int n = idx / D0, k = idx - n * D0;
        float w1 = W1[(size_t)k * D1 + n];
        float w2 = W2[(size_t)k * D1 + n];
        __nv_bfloat16 hi, lo;
        split_bf16(w1, hi, lo);
        g_w1hiT[idx] = hi; g_w1loT[idx] = lo;
        split_bf16(w2, hi, lo);
        g_w2hiT[idx] = hi; g_w2loT[idx] = lo;
    }
    if (idx < PREP_TOTAL) {
        int n = idx / (D0 / 8);
        int q = (idx - n * (D0 / 8)) * 8;
        const float* src = ((n < N_ITEMS) ? item + (size_t)n * D0
                                          : user + (size_t)(n - N_ITEMS) * D0) + q;
        float4 a = __ldg((const float4*)src);
        float4 b = __ldg((const float4*)(src + 4));
        uint4 o;
        o.x = pack_bf16(__float2bfloat16(a.x), __float2bfloat16(a.y));
        o.y = pack_bf16(__float2bfloat16(a.z), __float2bfloat16(a.w));
        o.z = pack_bf16(__float2bfloat16(b.x), __float2bfloat16(b.y));
        o.w = pack_bf16(__float2bfloat16(b.z), __float2bfloat16(b.w));
        *(uint4*)(g_egobf + (size_t)n * D0 + q) = o;
    }
}

// ---------------- CSR build ----------------
__global__ void hist_kernel(const int* __restrict__ rows) {
    int e = blockIdx.x * blockDim.x + threadIdx.x;
    if (e < NEDGES) atomicAdd(&g_hist[rows[e]], 1);
}

__global__ void scan_local_kernel() {
    __shared__ int wsum[32];
    int tid = threadIdx.x, lane = tid & 31, wid = tid >> 5;
    int i = blockIdx.x * 1024 + tid;
    int v = (i < NNODES) ? g_hist[i] : 0;
    int x = v;
    #pragma unroll
    for (int off = 1; off < 32; off <<= 1) {
        int t = __shfl_up_sync(0xffffffffu, x, off);
        if (lane >= off) x += t;
    }
    if (lane == 31) wsum[wid] = x;
    __syncthreads();
    if (wid == 0) {
        int w = wsum[lane];
        #pragma unroll
        for (int off = 1; off < 32; off <<= 1) {
            int t = __shfl_up_sync(0xffffffffu, w, off);
            if (lane >= off) w += t;
        }
        wsum[lane] = w;
    }
    __syncthreads();
    int warp_off = (wid == 0) ? 0 : wsum[wid - 1];
    int incl = x + warp_off;
    if (i < NNODES) g_rowptr[i] = incl - v;
    if (tid == 1023) g_bsum[blockIdx.x] = incl;
}

// scan_add folds the bsum prefix: each block reduces g_bsum[0..bid-1] in-block.
__global__ void scan_add_kernel() {
    __shared__ int part[64];
    const int bid = blockIdx.x;
    const int tid = threadIdx.x;
    if (tid < 64)
        part[tid] = (tid < bid && tid < SCANB) ? g_bsum[tid] : 0;
    __syncthreads();
    #pragma unroll
    for (int off = 32; off > 0; off >>= 1) {
        if (tid < off) part[tid] += part[tid + off];
        __syncthreads();
    }
    const int offset = part[0];
    int i = bid * 1024 + tid;
    if (i < NNODES) {
        int val = g_rowptr[i] + offset;
        g_rowptr[i] = val;
        g_cursor[i] = val;
    }
    if (bid == SCANB - 1 && tid == 0)
        g_rowptr[NNODES] = offset + g_bsum[SCANB - 1];
}

__global__ void scatter_kernel(const int* __restrict__ rows,
                               const int* __restrict__ cols,
                               const float* __restrict__ vals) {
    int e = blockIdx.x * blockDim.x + threadIdx.x;
    if (e < NEDGES) {
        int r = rows[e];
        int p = atomicAdd(&g_cursor[r], 1);
        g_col_sorted[p] = cols[e];
        g_val_sorted[p] = vals[e];
    }
}

// ---------------- SpMM layer0: bf16 gather, 256-col chunks, unroll 8 --------
__global__ __launch_bounds__(256) void spmm0_chunk_kernel() {
    const int w = threadIdx.x >> 5;      // warp -> row
    const int lane = threadIdx.x & 31;   // lane -> 8 bf16 cols
    const int r = blockIdx.x * 8 + w;
    const int off = blockIdx.y * 256 + lane * 8;
    if (r >= NNODES) return;
    const int e0 = g_rowptr[r], e1 = g_rowptr[r + 1];
    float acc[8];
    #pragma unroll
    for (int q = 0; q < 8; ++q) acc[q] = 0.f;
    int e = e0;
    const int n8 = e0 + ((e1 - e0) & ~7);
    for (; e < n8; e += 8) {
        const __nv_bfloat16* p[8];
        float v[8];
        #pragma unroll
        for (int q = 0; q < 8; ++q) {
            int c = g_col_sorted[e + q];
            v[q] = g_val_sorted[e + q];
            p[q] = g_egobf + (size_t)c * D0 + off;
        }
        uint4 x[8];
        #pragma unroll
        for (int q = 0; q < 8; ++q) x[q] = __ldg((const uint4*)p[q]);
        #pragma unroll
        for (int q = 0; q < 8; ++q) {
            float2 p0 = __bfloat1622float2(*(__nv_bfloat162*)&x[q].x);
            float2 p1 = __bfloat1622float2(*(__nv_bfloat162*)&x[q].y);
            float2 p2 = __bfloat1622float2(*(__nv_bfloat162*)&x[q].z);
            float2 p3 = __bfloat1622float2(*(__nv_bfloat162*)&x[q].w);
            acc[0] += v[q] * p0.x; acc[1] += v[q] * p0.y;
            acc[2] += v[q] * p1.x; acc[3] += v[q] * p1.y;
            acc[4] += v[q] * p2.x; acc[5] += v[q] * p2.y;
            acc[6] += v[q] * p3.x; acc[7] += v[q] * p3.y;
        }
    }
    for (; e < e1; ++e) {
        int   c = g_col_sorted[e];
        float v = g_val_sorted[e];
        uint4 x = __ldg((const uint4*)(g_egobf + (size_t)c * D0 + off));
        float2 p0 = __bfloat1622float2(*(__nv_bfloat162*)&x.x);
        float2 p1 = __bfloat1622float2(*(__nv_bfloat162*)&x.y);
        float2 p2 = __bfloat1622float2(*(__nv_bfloat162*)&x.z);
        float2 p3 = __bfloat1622float2(*(__nv_bfloat162*)&x.w);
        acc[0] += v * p0.x; acc[1] += v * p0.y;
        acc[2] += v * p1.x; acc[3] += v * p1.y;
        acc[4] += v * p2.x; acc[5] += v * p2.y;
        acc[6] += v * p3.x; acc[7] += v * p3.y;
    }
    uint4 o;
    o.x = pack_bf16(__float2bfloat16(acc[0]), __float2bfloat16(acc[1]));
    o.y = pack_bf16(__float2bfloat16(acc[2]), __float2bfloat16(acc[3]));
    o.z = pack_bf16(__float2bfloat16(acc[4]), __float2bfloat16(acc[5]));
    o.w = pack_bf16(__float2bfloat16(acc[6]), __float2bfloat16(acc[7]));
    *(uint4*)(g_side0bf + (size_t)r * D0 + off) = o;
}

// ---------------- fused GEMM layer0 (mma.sync bf16, 3-term split) ----------------
#define APAD 24   // row stride in bf16 (48 B, conflict-free ldmatrix)

__global__ __launch_bounds__(128) void gemm0_mma_kernel(
    const float* __restrict__ item, const float* __restrict__ user,
    const float* __restrict__ b1, const float* __restrict__ b2,
    float* __restrict__ out) {
    __shared__ __align__(16) __nv_bfloat16 sAhi[64 * APAD];
    __shared__ __align__(16) __nv_bfloat16 sAlo[64 * APAD];
    __shared__ __align__(16) __nv_bfloat16 sHhi[64 * APAD];
    __shared__ __align__(16) __nv_bfloat16 sHlo[64 * APAD];
    __shared__ __align__(16) __nv_bfloat16 sW1h[128 * APAD];
    __shared__ __align__(16) __nv_bfloat16 sW1l[128 * APAD];
    __shared__ __align__(16) __nv_bfloat16 sW2h[128 * APAD];
    __shared__ __align__(16) __nv_bfloat16 sW2l[128 * APAD];
    __shared__ float bsum[D1];
    __shared__ float rowss[64];

    const int t    = threadIdx.x;
    const int lane = t & 31;
    const int wid  = t >> 5;
    const int wm   = wid >> 1;
    const int wn   = wid & 1;
    const int rm   = blockIdx.x * 64;

    bsum[t] = b1[t] + b2[t];
    if (t < 64) rowss[t] = 0.f;

    const int arow = t >> 1;
    const int akq  = (t & 1) * 8;
    const int gm   = rm + arow;
    const bool mOk = gm < NNODES;
    const __nv_bfloat16* sideRow = g_side0bf + (size_t)gm * D0 + akq;
    const float* egoRow  = ((gm < N_ITEMS) ? item + (size_t)gm * D0
                                           : user + (size_t)(gm - N_ITEMS) * D0) + akq;
    float* outRow = out + (size_t)gm * OUTW + akq;

    const uint32_t aOff = (uint32_t)(((wm * 32 + (lane & 15)) * APAD + (lane >> 4) * 8) * 2);
    const uint32_t addrAhi = smem_u32(sAhi) + aOff;
    const uint32_t addrAlo = smem_u32(sAlo) + aOff;
    const uint32_t addrHhi = smem_u32(sHhi) + aOff;
    const uint32_t addrHlo = smem_u32(sHlo) + aOff;
    const uint32_t bOff4 = (uint32_t)(((wn * 64 + (lane & 7) + ((lane >> 4) << 3)) * APAD
                                       + ((lane >> 3) & 1) * 8) * 2);
    const uint32_t addrW1h = smem_u32(sW1h) + bOff4;
    const uint32_t addrW1l = smem_u32(sW1l) + bOff4;
    const uint32_t addrW2h = smem_u32(sW2h) + bOff4;
    const uint32_t addrW2l = smem_u32(sW2l) + bOff4;
    const uint32_t MT  = 16 * APAD * 2;
    const uint32_t J2T = 16 * APAD * 2;

    float acc[2][8][4];
    #pragma unroll
    for (int i = 0; i < 2; ++i)
        #pragma unroll
        for (int j = 0; j < 8; ++j)
            #pragma unroll
            for (int q = 0; q < 4; ++q) acc[i][j][q] = 0.f;

    for (int kt = 0; kt < D0; kt += 16) {
        {
            float sv[8];
            float4 ea, eb;
            if (mOk) {
                uint4 sx = __ldg((const uint4*)(sideRow + kt));
                float2 q0 = __bfloat1622float2(*(__nv_bfloat162*)&sx.x);
                float2 q1 = __bfloat1622float2(*(__nv_bfloat162*)&sx.y);
                float2 q2 = __bfloat1622float2(*(__nv_bfloat162*)&sx.z);
                float2 q3 = __bfloat1622float2(*(__nv_bfloat162*)&sx.w);
                sv[0] = q0.x; sv[1] = q0.y; sv[2] = q1.x; sv[3] = q1.y;
                sv[4] = q2.x; sv[5] = q2.y; sv[6] = q3.x; sv[7] = q3.y;
                ea = __ldg((const float4*)(egoRow + kt));
                eb = __ldg((const float4*)(egoRow + kt + 4));
                *(float4*)(outRow + kt) = ea;
                *(float4*)(outRow + kt + 4) = eb;
            } else {
                #pragma unroll
                for (int q = 0; q < 8; ++q) sv[q] = 0.f;
                ea = make_float4(0.f, 0.f, 0.f, 0.f);
                eb = ea;
            }
            float ev[8] = {ea.x, ea.y, ea.z, ea.w, eb.x, eb.y, eb.z, eb.w};
            float av[8], hv[8];
            #pragma unroll
            for (int q = 0; q < 8; ++q) {
                av[q] = sv[q] + ev[q];
                hv[q] = sv[q] * ev[q];
            }
            uint4 uahi, ualo, uhhi, uhlo;
            uint32_t* pa = (uint32_t*)&uahi; uint32_t* pl = (uint32_t*)&ualo;
            uint32_t* ph = (uint32_t*)&uhhi; uint32_t* pm = (uint32_t*)&uhlo;
            __nv_bfloat16 h0, l0, h1, l1;
            #pragma unroll
            for (int q = 0; q < 4; ++q) {
                split_bf16(av[2 * q], h0, l0);
                split_bf16(av[2 * q + 1], h1, l1);
                pa[q] = pack_bf16(h0, h1);
                pl[q] = pack_bf16(l0, l1);
                split_bf16(hv[2 * q], h0, l0);
                split_bf16(hv[2 * q + 1], h1, l1);
                ph[q] = pack_bf16(h0, h1);
                pm[q] = pack_bf16(l0, l1);
            }
            int d = arow * APAD + akq;
            *(uint4*)(sAhi + d) = uahi;
            *(uint4*)(sAlo + d) = ualo;
            *(uint4*)(sHhi + d) = uhhi;
            *(uint4*)(sHlo + d) = uhlo;
        }
        #pragma unroll
        for (int s = 0; s < 2; ++s) {
            int g = s * 128 + t;
            int n = g >> 1;
            int kq = (g & 1) * 8;
            size_t src = (size_t)n * D0 + kt + kq;
            int d = n * APAD + kq;
            *(uint4*)(sW1h + d) = __ldg((const uint4*)(g_w1hiT + src));
            *(uint4*)(sW1l + d) = __ldg((const uint4*)(g_w1loT + src));
            *(uint4*)(sW2h + d) = __ldg((const uint4*)(g_w2hiT + src));
            *(uint4*)(sW2l + d) = __ldg((const uint4*)(g_w2loT + src));
        }
        __syncthreads();

        uint32_t fAhi[2][4], fAlo[2][4], fHhi[2][4], fHlo[2][4];
        ldsm_x4(fAhi[0], addrAhi);       ldsm_x4(fAhi[1], addrAhi + MT);
        ldsm_x4(fAlo[0], addrAlo);       ldsm_x4(fAlo[1], addrAlo + MT);
        ldsm_x4(fHhi[0], addrHhi);       ldsm_x4(fHhi[1], addrHhi + MT);
        ldsm_x4(fHlo[0], addrHlo);       ldsm_x4(fHlo[1], addrHlo + MT);

        #pragma unroll
        for (int jj = 0; jj < 4; ++jj) {
            const int j0 = 2 * jj, j1 = 2 * jj + 1;
            uint32_t b1h[4], b1l[4], b2h[4], b2l[4];
            ldsm_x4(b1h, addrW1h + jj * J2T);
            ldsm_x4(b1l, addrW1l + jj * J2T);
            ldsm_x4(b2h, addrW2h + jj * J2T);
            ldsm_x4(b2l, addrW2l + jj * J2T);
            mma_bf16(acc[0][j0], fAhi[0], b1h);
            mma_bf16(acc[1][j0], fAhi[1], b1h);
            mma_bf16(acc[0][j1], fAhi[0], b1h + 2);
            mma_bf16(acc[1][j1], fAhi[1], b1h + 2);
            mma_bf16(acc[0][j0], fAlo[0], b1h);
            mma_bf16(acc[1][j0], fAlo[1], b1h);
            mma_bf16(acc[0][j1], fAlo[0], b1h + 2);
            mma_bf16(acc[1][j1], fAlo[1], b1h + 2);
            mma_bf16(acc[0][j0], fAhi[0], b1l);
            mma_bf16(acc[1][j0], fAhi[1], b1l);
            mma_bf16(acc[0][j1], fAhi[0], b1l + 2);
            mma_bf16(acc[1][j1], fAhi[1], b1l + 2);
            mma_bf16(acc[0][j0], fHhi[0], b2h);
            mma_bf16(acc[1][j0], fHhi[1], b2h);
            mma_bf16(acc[0][j1], fHhi[0], b2h + 2);
            mma_bf16(acc[1][j1], fHhi[1], b2h + 2);
            mma_bf16(acc[0][j0], fHlo[0], b2h);
            mma_bf16(acc[1][j0], fHlo[1], b2h);
            mma_bf16(acc[0][j1], fHlo[0], b2h + 2);
            mma_bf16(acc[1][j1], fHlo[1], b2h + 2);
            mma_bf16(acc[0][j0], fHhi[0], b2l);
            mma_bf16(acc[1][j0], fHhi[1], b2l);
            mma_bf16(acc[0][j1], fHhi[0], b2l + 2);
            mma_bf16(acc[1][j1], fHhi[1], b2l + 2);
        }
        __syncthreads();
    }

    float vals[2][8][4];
    #pragma unroll
    for (int mt = 0; mt < 2; ++mt) {
        float s0 = 0.f, s1 = 0.f;
        #pragma unroll
        for (int j = 0; j < 8; ++j) {
            int col = wn * 64 + j * 8 + (lane & 3) * 2;
            float bc0 = bsum[col], bc1 = bsum[col + 1];
            float v0 = leaky(acc[mt][j][0] + bc0);
            float v1 = leaky(acc[mt][j][1] + bc1);
            float v2 = leaky(acc[mt][j][2] + bc0);
            float v3 = leaky(acc[mt][j][3] + bc1);
            vals[mt][j][0] = v0; vals[mt][j][1] = v1;
            vals[mt][j][2] = v2; vals[mt][j][3] = v3;
            s0 += v0 * v0 + v1 * v1;
            s1 += v2 * v2 + v3 * v3;
        }
        int lr0 = wm * 32 + mt * 16 + (lane >> 2);
        atomicAdd(&rowss[lr0], s0);
        atomicAdd(&rowss[lr0 + 8], s1);
    }
    __syncthreads();

    #pragma unroll
    for (int mt = 0; mt < 2; ++mt) {
        int lr0 = wm * 32 + mt * 16 + (lane >> 2);
        int row0 = rm + lr0;
        int row1 = row0 + 8;
        float inv0 = 1.f / fmaxf(sqrtf(rowss[lr0]), 1e-12f);
        float inv1 = 1.f / fmaxf(sqrtf(rowss[lr0 + 8]), 1e-12f);
        #pragma unroll
        for (int j = 0; j < 8; ++j) {
            int col = wn * 64 + j * 8 + (lane & 3) * 2;
            if (row0 < NNODES) {
                float2 o = make_float2(vals[mt][j][0], vals[mt][j][1]);
                *(float2*)(g_ego1 + (size_t)row0 * D1 + col) = o;
                *(uint32_t*)(g_ego1bf + (size_t)row0 * D1 + col) =
                    pack_bf16(__float2bfloat16(o.x), __float2bfloat16(o.y));
                float2 n = make_float2(o.x * inv0, o.y * inv0);
                *(float2*)(out + (size_t)row0 * OUTW + D0 + col) = n;
            }
            if (row1 < NNODES) {
                float2 o = make_float2(vals[mt][j][2], vals[mt][j][3]);
                *(float2*)(g_ego1 + (size_t)row1 * D1 + col) = o;
                *(uint32_t*)(g_ego1bf + (size_t)row1 * D1 + col) =
                    pack_bf16(__float2bfloat16(o.x), __float2bfloat16(o.y));
                float2 n = make_float2(o.x * inv1, o.y * inv1);
                *(float2*)(out + (size_t)row1 * OUTW + D0 + col) = n;
            }
        }
    }
}

// ---------------- SpMM layer1: side1 = A @ ego1bf (unroll 4) ----------------
__global__ void spmm1_kernel() {
    int w = threadIdx.x >> 5;
    int lane = threadIdx.x & 31;
    int r = blockIdx.x * 4 + w;
    if (r >= NNODES) return;
    int e0 = g_rowptr[r], e1 = g_rowptr[r + 1];
    float4 acc = make_float4(0.f, 0.f, 0.f, 0.f);
    int e = e0;
    int n4 = e0 + ((e1 - e0) & ~3);
    for (; e < n4; e += 4) {
        int c0 = g_col_sorted[e + 0], c1 = g_col_sorted[e + 1];
        int c2 = g_col_sorted[e + 2], c3 = g_col_sorted[e + 3];
        float v0 = g_val_sorted[e + 0], v1 = g_val_sorted[e + 1];
        float v2 = g_val_sorted[e + 2], v3 = g_val_sorted[e + 3];
        uint2 x0 = __ldg((const uint2*)(g_ego1bf + (size_t)c0 * D1 + lane * 4));
        uint2 x1 = __ldg((const uint2*)(g_ego1bf + (size_t)c1 * D1 + lane * 4));
        uint2 x2 = __ldg((const uint2*)(g_ego1bf + (size_t)c2 * D1 + lane * 4));
        uint2 x3 = __ldg((const uint2*)(g_ego1bf + (size_t)c3 * D1 + lane * 4));
        float2 a0 = __bfloat1622float2(*(__nv_bfloat162*)&x0.x);
        float2 b0 = __bfloat1622float2(*(__nv_bfloat162*)&x0.y);
        float2 a1 = __bfloat1622float2(*(__nv_bfloat162*)&x1.x);
        float2 b1 = __bfloat1622float2(*(__nv_bfloat162*)&x1.y);
        float2 a2 = __bfloat1622float2(*(__nv_bfloat162*)&x2.x);
        float2 b2 = __bfloat1622float2(*(__nv_bfloat162*)&x2.y);
        float2 a3 = __bfloat1622float2(*(__nv_bfloat162*)&x3.x);
        float2 b3 = __bfloat1622float2(*(__nv_bfloat162*)&x3.y);
        acc.x += v0 * a0.x + v1 * a1.x + v2 * a2.x + v3 * a3.x;
        acc.y += v0 * a0.y + v1 * a1.y + v2 * a2.y + v3 * a3.y;
        acc.z += v0 * b0.x + v1 * b1.x + v2 * b2.x + v3 * b3.x;
        acc.w += v0 * b0.y + v1 * b1.y + v2 * b2.y + v3 * b3.y;
    }
    for (; e < e1; ++e) {
        int   c = g_col_sorted[e];
        float v = g_val_sorted[e];
        uint2 x = __ldg((const uint2*)(g_ego1bf + (size_t)c * D1 + lane * 4));
        float2 a = __bfloat1622float2(*(__nv_bfloat162*)&x.x);
        float2 b = __bfloat1622float2(*(__nv_bfloat162*)&x.y);
        acc.x += v * a.x; acc.y += v * a.y; acc.z += v * b.x; acc.w += v * b.y;
    }
    *(float4*)(g_side1 + (size_t)r * D1 + lane * 4) = acc;
}

// ---------------- fused GEMM layer1 + normalize -> out[:, 896:960] ----------------
__global__ __launch_bounds__(256) void gemm1_kernel(
    const float* __restrict__ W1, const float* __restrict__ b1,
    const float* __restrict__ W2, const float* __restrict__ b2,
    float* __restrict__ out) {
    __shared__ __align__(16) float As[16][68];
    __shared__ __align__(16) float Hs[16][68];
    __shared__ __align__(16) float W1s[16][64];
    __shared__ __align__(16) float W2s[16][64];

    int t  = threadIdx.x;
    int tx = t & 31, ty = t >> 5;
    int rm = blockIdx.x * 64;

    float acc[8][2];
    #pragma unroll
    for (int i = 0; i < 8; ++i) { acc[i][0] = 0.f; acc[i][1] = 0.f; }

    int ml = t >> 2;
    int kl = (t & 3) * 4;
    int gm = rm + ml;
    bool mOk = gm < NNODES;
    int wk = t >> 4;
    int wj = (t & 15) * 4;

    for (int kt = 0; kt < D1; kt += 16) {
        if (mOk) {
            float4 s4 = *(const float4*)(g_side1 + (size_t)gm * D1 + kt + kl);
            float4 e4 = *(const float4*)(g_ego1  + (size_t)gm * D1 + kt + kl);
            As[kl + 0][ml] = s4.x + e4.x;  Hs[kl + 0][ml] = s4.x * e4.x;
            As[kl + 1][ml] = s4.y + e4.y;  Hs[kl + 1][ml] = s4.y * e4.y;
            As[kl + 2][ml] = s4.z + e4.z;  Hs[kl + 2][ml] = s4.z * e4.z;
            As[kl + 3][ml] = s4.w + e4.w;  Hs[kl + 3][ml] = s4.w * e4.w;
        } else {
            As[kl + 0][ml] = 0.f; Hs[kl + 0][ml] = 0.f;
            As[kl + 1][ml] = 0.f; Hs[kl + 1][ml] = 0.f;
            As[kl + 2][ml] = 0.f; Hs[kl + 2][ml] = 0.f;
            As[kl + 3][ml] = 0.f; Hs[kl + 3][ml] = 0.f;
        }
        *(float4*)&W1s[wk][wj] = *(const float4*)(W1 + (size_t)(kt + wk) * D2 + wj);
        *(float4*)&W2s[wk][wj] = *(const float4*)(W2 + (size_t)(kt + wk) * D2 + wj);
        __syncthreads();

        #pragma unroll
        for (int k = 0; k < 16; ++k) {
            float2 w1 = *(const float2*)&W1s[k][tx * 2];
            float2 w2 = *(const float2*)&W2s[k][tx * 2];
            float4 a0 = *(const float4*)&As[k][ty * 8];
            float4 a1 = *(const float4*)&As[k][ty * 8 + 4];
            float4 h0 = *(const float4*)&Hs[k][ty * 8];
            float4 h1 = *(const float4*)&Hs[k][ty * 8 + 4];
            float a[8] = {a0.x, a0.y, a0.z, a0.w, a1.x, a1.y, a1.z, a1.w};
            float h[8] = {h0.x, h0.y, h0.z, h0.w, h1.x, h1.y, h1.z, h1.w};
            #pragma unroll
            for (int i = 0; i < 8; ++i) {
                acc[i][0] += a[i] * w1.x + h[i] * w2.x;
                acc[i][1] += a[i] * w1.y + h[i] * w2.y;
            }
        }
        __syncthreads();
    }

    int jc = tx * 2;
    float bs0 = b1[jc] + b2[jc];
    float bs1 = b1[jc + 1] + b2[jc + 1];
    #pragma unroll
    for (int i = 0; i < 8; ++i) {
        int row = rm + ty * 8 + i;
        float v0 = leaky(acc[i][0] + bs0);
        float v1 = leaky(acc[i][1] + bs1);
        float ss = v0 * v0 + v1 * v1;
        #pragma unroll
        for (int off = 16; off > 0; off >>= 1)
            ss += __shfl_xor_sync(0xffffffffu, ss, off);
        float inv = 1.f / fmaxf(sqrtf(ss), 1e-12f);
        if (row < NNODES) {
            float2 o = make_float2(v0 * inv, v1 * inv);
            *(float2*)(out + (size_t)row * OUTW + (D0 + D1) + jc) = o;
        }
    }
}

// ---------------- launch (9 kernels) ----------------
extern "C" void kernel_launch(void* const* d_in, const int* in_sizes, int n_in,
                              void* d_out, int out_size) {
    const float* item  = (const float*)d_in[0];
    const float* user  = (const float*)d_in[1];
    const float* W1_0  = (const float*)d_in[2];
    const float* b1_0  = (const float*)d_in[3];
    const float* W2_0  = (const float*)d_in[4];
    const float* b2_0  = (const float*)d_in[5];
    const float* W1_1  = (const float*)d_in[6];
    const float* b1_1  = (const float*)d_in[7];
    const float* W2_1  = (const float*)d_in[8];
    const float* b2_1  = (const float*)d_in[9];
    const float* evals = (const float*)d_in[10];
    const int*   erows = (const int*)d_in[11];
    const int*   ecols = (const int*)d_in[12];
    float* out = (float*)d_out;

    prep_kernel<<<(PREP_TOTAL + 255) / 256, 256>>>(item, user, W1_0, W2_0);
    hist_kernel<<<(NEDGES + 255) / 256, 256>>>(erows);
    scan_local_kernel<<<SCANB, 1024>>>();
    scan_add_kernel<<<SCANB, 1024>>>();
    scatter_kernel<<<(NEDGES + 255) / 256, 256>>>(erows, ecols, evals);

    {
        dim3 grid((NNODES + 7) / 8, D0 / 256);   // 3 feature chunks (slow dim)
        spmm0_chunk_kernel<<<grid, 256>>>();
    }
    gemm0_mma_kernel<<<(NNODES + 63) / 64, 128>>>(item, user, b1_0, b2_0, out);
    spmm1_kernel<<<(NNODES + 3) / 4, 128>>>();
    gemm1_kernel<<<(NNODES + 63) / 64, 256>>>(W1_1, b1_1, W2_1, b2_1, out);
}